// round 8
// baseline (speedup 1.0000x reference)
#include <cuda_runtime.h>
#include <mma.h>
#include <math.h>

using namespace nvcuda;

#define HIDN   2048
#define INTERN 4096
#define CONVD  6144
#define PROJN  10304
#define NHEAD  64
#define HEADP  64
#define NGRP   8
#define NSTATE 128
#define CHUNK  256
#define LSEQ   2048
#define NBATCH 2
#define NCHUNK 8
#define BT     4096          // total tokens
#define NBC    16            // NBATCH*NCHUNK
#define EPSV   1e-5f

// ---------------- scratch (device globals; no allocation) ----------------
__device__ float g_zx[(size_t)BT * PROJN];        // in_proj output
__device__ float g_xbc[(size_t)BT * CONVD];       // conv+silu output
__device__ float g_dtsp[BT * NHEAD];              // softplus(dt)
__device__ float g_dacs[BT * NHEAD];              // cumsum(dt*A) per chunk
__device__ float g_states[(size_t)NBC * NHEAD * HEADP * NSTATE];
__device__ float g_prev[(size_t)NBC * NHEAD * HEADP * NSTATE];
__device__ float g_y[(size_t)BT * INTERN];

__device__ __forceinline__ float to_tf32_rn(float x) {
    float r;
    asm("cvt.rna.tf32.f32 %0, %1;" : "=f"(r) : "f"(x));
    return r;
}

// ---------------- TF32 tensor-core GEMM: C[M,N] = A[M,K] * B[N,K]^T ----------
// Double-buffered software pipeline. 128x128 block tile, BK=32,
// 256 threads = 8 warps, each warp 64x32 (4x2 wmma m16n16k8 tiles).
#define LDA 40
#define STAGE_F (128 * LDA)

__global__ __launch_bounds__(256) void gemm_tf32(
    const float* __restrict__ A, const float* __restrict__ B,
    float* __restrict__ C, int M, int N, int K)
{
    extern __shared__ float sm[];
    float* Asm = sm;                    // [2][128*LDA]
    float* Bsm = sm + 2 * STAGE_F;      // [2][128*LDA]

    int bm = blockIdx.y * 128;
    int bn = blockIdx.x * 128;
    int tid = threadIdx.x;
    int wid = tid >> 5;
    int wm = wid >> 2;          // 0..1  (64-row strip)
    int wn = wid & 3;           // 0..3  (32-col strip)

    // staging mapping: each thread handles 16 consecutive floats (4 x float4)
    int srow = tid >> 1;              // 0..127
    int skc  = (tid & 1) * 16;        // 0 or 16

    const float* Ag = A + (size_t)(bm + srow) * K + skc;
    int brow = bn + srow;
    bool bvalid = brow < N;
    const float* Bg = B + (size_t)(bvalid ? brow : 0) * K + skc;

    wmma::fragment<wmma::accumulator, 16, 16, 8, float> acc[4][2];
    #pragma unroll
    for (int i = 0; i < 4; i++)
        #pragma unroll
        for (int j = 0; j < 2; j++)
            wmma::fill_fragment(acc[i][j], 0.0f);

    float4 ar[4], br[4];

    // prologue: load + stage tile 0
    #pragma unroll
    for (int v = 0; v < 4; v++) {
        ar[v] = *(const float4*)(Ag + v * 4);
        br[v] = bvalid ? *(const float4*)(Bg + v * 4) : make_float4(0.f,0.f,0.f,0.f);
    }
    #pragma unroll
    for (int v = 0; v < 4; v++) {
        float* da = &Asm[srow * LDA + skc + v * 4];
        da[0] = to_tf32_rn(ar[v].x); da[1] = to_tf32_rn(ar[v].y);
        da[2] = to_tf32_rn(ar[v].z); da[3] = to_tf32_rn(ar[v].w);
        float* db = &Bsm[srow * LDA + skc + v * 4];
        db[0] = to_tf32_rn(br[v].x); db[1] = to_tf32_rn(br[v].y);
        db[2] = to_tf32_rn(br[v].z); db[3] = to_tf32_rn(br[v].w);
    }
    __syncthreads();

    int nk = K >> 5;
    int buf = 0;
    for (int t = 0; t < nk; t++) {
        bool has_next = (t + 1 < nk);
        // issue global loads for next tile (latency hidden behind mma)
        if (has_next) {
            int koff = (t + 1) * 32;
            #pragma unroll
            for (int v = 0; v < 4; v++) {
                ar[v] = *(const float4*)(Ag + koff + v * 4);
                br[v] = bvalid ? *(const float4*)(Bg + koff + v * 4)
                               : make_float4(0.f,0.f,0.f,0.f);
            }
        }

        // compute on current stage
        const float* Ab = Asm + buf * STAGE_F;
        const float* Bb = Bsm + buf * STAGE_F;
        #pragma unroll
        for (int ks = 0; ks < 4; ks++) {
            wmma::fragment<wmma::matrix_a, 16, 16, 8, wmma::precision::tf32, wmma::row_major> af[4];
            wmma::fragment<wmma::matrix_b, 16, 16, 8, wmma::precision::tf32, wmma::col_major> bf[2];
            #pragma unroll
            for (int i = 0; i < 4; i++)
                wmma::load_matrix_sync(af[i], &Ab[(wm * 64 + i * 16) * LDA + ks * 8], LDA);
            #pragma unroll
            for (int j = 0; j < 2; j++)
                wmma::load_matrix_sync(bf[j], &Bb[(wn * 32 + j * 16) * LDA + ks * 8], LDA);
            #pragma unroll
            for (int i = 0; i < 4; i++)
                #pragma unroll
                for (int j = 0; j < 2; j++)
                    wmma::mma_sync(acc[i][j], af[i], bf[j], acc[i][j]);
        }

        // stage next tile into the other buffer
        if (has_next) {
            float* da0 = Asm + (buf ^ 1) * STAGE_F + srow * LDA + skc;
            float* db0 = Bsm + (buf ^ 1) * STAGE_F + srow * LDA + skc;
            #pragma unroll
            for (int v = 0; v < 4; v++) {
                float* da = da0 + v * 4;
                da[0] = to_tf32_rn(ar[v].x); da[1] = to_tf32_rn(ar[v].y);
                da[2] = to_tf32_rn(ar[v].z); da[3] = to_tf32_rn(ar[v].w);
                float* db = db0 + v * 4;
                db[0] = to_tf32_rn(br[v].x); db[1] = to_tf32_rn(br[v].y);
                db[2] = to_tf32_rn(br[v].z); db[3] = to_tf32_rn(br[v].w);
            }
        }
        __syncthreads();
        buf ^= 1;
    }

    // epilogue (N columns are multiples of 16 here: 10304, 2048)
    #pragma unroll
    for (int i = 0; i < 4; i++) {
        int r0 = bm + wm * 64 + i * 16;
        #pragma unroll
        for (int j = 0; j < 2; j++) {
            int c0 = bn + wn * 32 + j * 16;
            if (c0 < N)
                wmma::store_matrix_sync(&C[(size_t)r0 * N + c0], acc[i][j], N, wmma::mem_row_major);
        }
    }
}

// ---------------- conv1d (K=4, causal, per-batch padding) + SiLU -------------
__global__ void conv_silu_kernel(const float* __restrict__ cw, const float* __restrict__ cb)
{
    int c = blockIdx.x * 256 + threadIdx.x;
    int t = blockIdx.y;
    if (c >= CONVD) return;
    int pos = t & (LSEQ - 1);
    const float* col = g_zx + INTERN + c;
    float w0 = cw[c*4+0], w1 = cw[c*4+1], w2 = cw[c*4+2], w3 = cw[c*4+3];
    float v = cb[c];
    float x3 = col[(size_t)t * PROJN];
    float x2 = (pos >= 1) ? col[(size_t)(t-1) * PROJN] : 0.f;
    float x1 = (pos >= 2) ? col[(size_t)(t-2) * PROJN] : 0.f;
    float x0 = (pos >= 3) ? col[(size_t)(t-3) * PROJN] : 0.f;
    v += w0*x0 + w1*x1 + w2*x2 + w3*x3;
    g_xbc[(size_t)t * CONVD + c] = v / (1.f + expf(-v));
}

// ---------------- dt: softplus + dA cumsum per chunk -------------------------
__global__ void dt_kernel(const float* __restrict__ dtb, const float* __restrict__ alog)
{
    int bc = blockIdx.x;       // 0..15
    int h = threadIdx.x;       // 0..63
    int t0 = bc * CHUNK;
    float bias = dtb[h];
    float A = -expf(alog[h]);
    float cs = 0.f;
    for (int j = 0; j < CHUNK; j++) {
        int t = t0 + j;
        float raw = g_zx[(size_t)t * PROJN + INTERN + CONVD + h] + bias;
        float dtv = (raw > 20.f) ? raw : log1pf(expf(raw));
        g_dtsp[t * NHEAD + h] = dtv;
        cs += dtv * A;
        g_dacs[t * NHEAD + h] = cs;
    }
}

// ---------------- per-chunk states: S[p,n] = sum_j x[j,p] w[j] B[j,n] --------
__global__ __launch_bounds__(256) void states_kernel()
{
    int h = blockIdx.x, bc = blockIdx.y;
    int g = h >> 3;
    int t0 = bc * CHUNK;
    int tlast = t0 + CHUNK - 1;
    __shared__ float xw[32][64];
    __shared__ float Bs[32][128];
    __shared__ float ws[32];
    int tid = threadIdx.x;
    int tp = tid & 15;     // p block of 4
    int tn = tid >> 4;     // n block of 8
    float acc[4][8];
    #pragma unroll
    for (int i = 0; i < 4; i++)
        #pragma unroll
        for (int k = 0; k < 8; k++) acc[i][k] = 0.f;
    float daL = g_dacs[tlast * NHEAD + h];

    for (int j0 = 0; j0 < CHUNK; j0 += 32) {
        if (tid < 32) {
            int t = t0 + j0 + tid;
            ws[tid] = expf(daL - g_dacs[t * NHEAD + h]) * g_dtsp[t * NHEAD + h];
        }
        __syncthreads();
        for (int e = tid; e < 32*64; e += 256) {
            int j = e >> 6, p = e & 63;
            int t = t0 + j0 + j;
            xw[j][p] = g_xbc[(size_t)t * CONVD + h * HEADP + p] * ws[j];
        }
        for (int e = tid; e < 32*128; e += 256) {
            int j = e >> 7, n = e & 127;
            int t = t0 + j0 + j;
            Bs[j][n] = g_xbc[(size_t)t * CONVD + INTERN + g * NSTATE + n];
        }
        __syncthreads();
        #pragma unroll 4
        for (int j = 0; j < 32; j++) {
            float4 xv = *(const float4*)&xw[j][tp*4];
            float4 b0 = *(const float4*)&Bs[j][tn*8];
            float4 b1 = *(const float4*)&Bs[j][tn*8+4];
            float xr[4] = {xv.x, xv.y, xv.z, xv.w};
            float br[8] = {b0.x,b0.y,b0.z,b0.w,b1.x,b1.y,b1.z,b1.w};
            #pragma unroll
            for (int i = 0; i < 4; i++)
                #pragma unroll
                for (int k = 0; k < 8; k++)
                    acc[i][k] += xr[i] * br[k];
        }
        __syncthreads();
    }
    float* S = g_states + ((size_t)bc * NHEAD + h) * HEADP * NSTATE;
    #pragma unroll
    for (int i = 0; i < 4; i++)
        #pragma unroll
        for (int k = 0; k < 8; k++)
            S[(tp*4 + i) * NSTATE + tn*8 + k] = acc[i][k];
}

// ---------------- inter-chunk scan ------------------------------------------
__global__ void scan_kernel()
{
    int b = blockIdx.x >> 6;
    int h = blockIdx.x & 63;
    for (int e = threadIdx.x; e < HEADP * NSTATE; e += 256) {
        float run = 0.f;
        for (int z = 0; z < NCHUNK; z++) {
            int bc = b * NCHUNK + z;
            size_t off = ((size_t)bc * NHEAD + h) * HEADP * NSTATE + e;
            g_prev[off] = run;
            int tlast = bc * CHUNK + CHUNK - 1;
            float dec = expf(g_dacs[tlast * NHEAD + h]);
            run = dec * run + g_states[off];
        }
    }
}

// ---------------- fused Y_diag + Y_off + D*x ---------------------------------
// block = (itile, h, bc); computes 64 tokens x 64 headdim
__global__ __launch_bounds__(256) void ymain_kernel(const float* __restrict__ Dp)
{
    int it = blockIdx.x, h = blockIdx.y, bc = blockIdx.z;
    int g = h >> 3;
    int t0 = bc * CHUNK;
    int i0 = it * 64;
    extern __shared__ float sm[];
    float* Cs  = sm;             // [64][129]
    float* Js  = Cs + 64*129;    // [64][129]  (prev or B_j)
    float* Xs  = Js + 64*129;    // [64][65]
    float* Ss  = Xs + 64*65;     // [64][65]
    float* dai = Ss + 64*65;     // [64]
    float* eiv = dai + 64;       // [64]
    float* daj = eiv + 64;       // [64]
    float* dtj = daj + 64;       // [64]

    int tid = threadIdx.x;
    int tx = tid & 15, ty = tid >> 4;

    // load C_i tile and dA_cs for i-rows
    for (int e = tid; e < 64*128; e += 256) {
        int i = e >> 7, n = e & 127;
        Cs[i*129 + n] = g_xbc[(size_t)(t0 + i0 + i) * CONVD + INTERN + NGRP*NSTATE + g*NSTATE + n];
    }
    if (tid < 64) {
        float d = g_dacs[(t0 + i0 + tid) * NHEAD + h];
        dai[tid] = d;
        eiv[tid] = expf(d);
    }
    // load prev state [p][n]
    const float* prev = g_prev + ((size_t)bc * NHEAD + h) * HEADP * NSTATE;
    for (int e = tid; e < 64*128; e += 256) {
        int p = e >> 7, n = e & 127;
        Js[p*129 + n] = prev[p * NSTATE + n];
    }
    __syncthreads();

    // Y_off: acc[i][p] = ei[i] * sum_n C[i,n]*prev[p,n]
    float acc[4][4];
    {
        float off[4][4];
        #pragma unroll
        for (int i = 0; i < 4; i++)
            #pragma unroll
            for (int p = 0; p < 4; p++) off[i][p] = 0.f;
        #pragma unroll 4
        for (int n = 0; n < 128; n++) {
            float a[4], bv[4];
            #pragma unroll
            for (int i = 0; i < 4; i++) a[i] = Cs[(ty*4 + i)*129 + n];
            #pragma unroll
            for (int p = 0; p < 4; p++) bv[p] = Js[(tx*4 + p)*129 + n];
            #pragma unroll
            for (int i = 0; i < 4; i++)
                #pragma unroll
                for (int p = 0; p < 4; p++) off[i][p] += a[i] * bv[p];
        }
        #pragma unroll
        for (int i = 0; i < 4; i++)
            #pragma unroll
            for (int p = 0; p < 4; p++) acc[i][p] = off[i][p] * eiv[ty*4 + i];
    }
    __syncthreads();

    // Y_diag: loop over j-tiles <= i-tile
    for (int jt = 0; jt <= it; jt++) {
        int j0 = jt * 64;
        for (int e = tid; e < 64*128; e += 256) {
            int j = e >> 7, n = e & 127;
            Js[j*129 + n] = g_xbc[(size_t)(t0 + j0 + j) * CONVD + INTERN + g*NSTATE + n];
        }
        for (int e = tid; e < 64*64; e += 256) {
            int j = e >> 6, p = e & 63;
            Xs[j*65 + p] = g_xbc[(size_t)(t0 + j0 + j) * CONVD + h * HEADP + p];
        }
        if (tid < 64) {
            int t = t0 + j0 + tid;
            daj[tid] = g_dacs[t * NHEAD + h];
            dtj[tid] = g_dtsp[t * NHEAD + h];
        }
        __syncthreads();

        // S = C_i . B_j^T over N=128
        float s[4][4];
        #pragma unroll
        for (int i = 0; i < 4; i++)
            #pragma unroll
            for (int j = 0; j < 4; j++) s[i][j] = 0.f;
        #pragma unroll 4
        for (int n = 0; n < 128; n++) {
            float a[4], bv[4];
            #pragma unroll
            for (int i = 0; i < 4; i++) a[i] = Cs[(ty*4 + i)*129 + n];
            #pragma unroll
            for (int j = 0; j < 4; j++) bv[j] = Js[(tx*4 + j)*129 + n];
            #pragma unroll
            for (int i = 0; i < 4; i++)
                #pragma unroll
                for (int j = 0; j < 4; j++) s[i][j] += a[i] * bv[j];
        }
        // mask + decay + dt, stage to smem
        #pragma unroll
        for (int ii = 0; ii < 4; ii++) {
            int il = ty*4 + ii;
            int ig = i0 + il;
            #pragma unroll
            for (int jj = 0; jj < 4; jj++) {
                int jl = tx*4 + jj;
                int jg = j0 + jl;
                float v = 0.f;
                if (ig >= jg) v = s[ii][jj] * expf(dai[il] - daj[jl]) * dtj[jl];
                Ss[il*65 + jl] = v;
            }
        }
        __syncthreads();
        // acc += S @ x_j
        #pragma unroll 4
        for (int j = 0; j < 64; j++) {
            float a[4], bv[4];
            #pragma unroll
            for (int i = 0; i < 4; i++) a[i] = Ss[(ty*4 + i)*65 + j];
            #pragma unroll
            for (int p = 0; p < 4; p++) bv[p] = Xs[j*65 + tx*4 + p];
            #pragma unroll
            for (int i = 0; i < 4; i++)
                #pragma unroll
                for (int p = 0; p < 4; p++) acc[i][p] += a[i] * bv[p];
        }
        __syncthreads();
    }

    // epilogue: + D[h] * x_i ; write y
    float Dh = Dp[h];
    #pragma unroll
    for (int ii = 0; ii < 4; ii++) {
        int t = t0 + i0 + ty*4 + ii;
        #pragma unroll
        for (int pp = 0; pp < 4; pp++) {
            int p = tx*4 + pp;
            float xv = g_xbc[(size_t)t * CONVD + h * HEADP + p];
            g_y[(size_t)t * INTERN + h * HEADP + p] = acc[ii][pp] + Dh * xv;
        }
    }
}

// ---------------- RMS norm + silu(z) gate (in-place on g_y) ------------------
__global__ void normgate_kernel(const float* __restrict__ nw)
{
    int t = blockIdx.x;
    float s = 0.f;
    for (int c = threadIdx.x; c < INTERN; c += 256) {
        float v = g_y[(size_t)t * INTERN + c];
        s += v * v;
    }
    __shared__ float red[8];
    #pragma unroll
    for (int o = 16; o; o >>= 1) s += __shfl_xor_sync(0xffffffffu, s, o);
    if ((threadIdx.x & 31) == 0) red[threadIdx.x >> 5] = s;
    __syncthreads();
    if (threadIdx.x < 8) {
        float v = red[threadIdx.x];
        #pragma unroll
        for (int o = 4; o; o >>= 1) v += __shfl_xor_sync(0xffu, v, o);
        if (threadIdx.x == 0) red[0] = v;
    }
    __syncthreads();
    float inv = rsqrtf(red[0] / (float)INTERN + EPSV);
    for (int c = threadIdx.x; c < INTERN; c += 256) {
        float v = g_y[(size_t)t * INTERN + c] * inv * nw[c];
        float z = g_zx[(size_t)t * PROJN + c];
        g_y[(size_t)t * INTERN + c] = v * (z / (1.f + expf(-z)));
    }
}

// ---------------- launch ------------------------------------------------------
extern "C" void kernel_launch(void* const* d_in, const int* in_sizes, int n_in,
                              void* d_out, int out_size)
{
    const float* hs    = (const float*)d_in[0];
    const float* w_in  = (const float*)d_in[1];
    const float* cw    = (const float*)d_in[2];
    const float* cb    = (const float*)d_in[3];
    const float* dtb   = (const float*)d_in[4];
    const float* alog  = (const float*)d_in[5];
    const float* Dp    = (const float*)d_in[6];
    const float* nw    = (const float*)d_in[7];
    const float* w_out = (const float*)d_in[8];
    float* out = (float*)d_out;

    float *zx, *y;
    cudaGetSymbolAddress((void**)&zx, g_zx);
    cudaGetSymbolAddress((void**)&y, g_y);

    size_t gsmem = (size_t)4 * STAGE_F * sizeof(float);   // 2 stages x (A+B)
    cudaFuncSetAttribute(gemm_tf32, cudaFuncAttributeMaxDynamicSharedMemorySize, (int)gsmem);

    size_t ysmem = (size_t)(64*129*2 + 64*65*2 + 4*64) * sizeof(float);
    cudaFuncSetAttribute(ymain_kernel, cudaFuncAttributeMaxDynamicSharedMemorySize, (int)ysmem);

    // 1) in_proj GEMM: [4096,10304] = [4096,2048] x [10304,2048]^T  (tf32 TC)
    gemm_tf32<<<dim3((PROJN + 127) / 128, BT / 128), 256, gsmem>>>(hs, w_in, zx, BT, PROJN, HIDN);
    // 2) conv + silu
    conv_silu_kernel<<<dim3(CONVD / 256, BT), 256>>>(cw, cb);
    // 3) dt softplus + dA cumsum
    dt_kernel<<<NBC, NHEAD>>>(dtb, alog);
    // 4) per-chunk states
    states_kernel<<<dim3(NHEAD, NBC), 256>>>();
    // 5) inter-chunk scan
    scan_kernel<<<NBATCH * NHEAD, 256>>>();
    // 6) fused diag + off + D*x
    ymain_kernel<<<dim3(CHUNK / 64, NHEAD, NBC), 256, ysmem>>>(Dp);
    // 7) rmsnorm + gate
    normgate_kernel<<<BT, 256>>>(nw);
    // 8) out_proj GEMM: [4096,2048] = [4096,4096] x [2048,4096]^T  (tf32 TC)
    gemm_tf32<<<dim3(HIDN / 128, BT / 128), 256, gsmem>>>(y, w_out, out, BT, HIDN, INTERN);
}

// round 11
// speedup vs baseline: 1.0477x; 1.0477x over previous
#include <cuda_runtime.h>
#include <mma.h>
#include <math.h>
#include <cstdint>
#include <stdint.h>

using namespace nvcuda;

#define HIDN   2048
#define INTERN 4096
#define CONVD  6144
#define PROJN  10304
#define NHEAD  64
#define HEADP  64
#define NGRP   8
#define NSTATE 128
#define CHUNK  256
#define LSEQ   2048
#define NBATCH 2
#define NCHUNK 8
#define BT     4096          // total tokens
#define NBC    16            // NBATCH*NCHUNK
#define EPSV   1e-5f

// ---------------- scratch (device globals; no allocation) ----------------
__device__ float g_zx[(size_t)BT * PROJN];        // in_proj output
__device__ float g_xbc[(size_t)BT * CONVD];       // conv+silu output
__device__ float g_dtsp[BT * NHEAD];              // softplus(dt)
__device__ float g_dacs[BT * NHEAD];              // cumsum(dt*A) per chunk
__device__ float g_states[(size_t)NBC * NHEAD * HEADP * NSTATE];
__device__ float g_prev[(size_t)NBC * NHEAD * HEADP * NSTATE];
__device__ float g_y[(size_t)BT * INTERN];

__device__ __forceinline__ float to_tf32_rn(float x) {
    float r;
    asm("cvt.rna.tf32.f32 %0, %1;" : "=f"(r) : "f"(x));
    return r;
}

__device__ __forceinline__ void cp_async16(unsigned int saddr, const void* gptr, bool pred) {
    int sz = pred ? 16 : 0;
    asm volatile("cp.async.cg.shared.global [%0], [%1], 16, %2;"
                 :: "r"(saddr), "l"(gptr), "r"(sz) : "memory");
}
__device__ __forceinline__ void cp_commit() {
    asm volatile("cp.async.commit_group;" ::: "memory");
}
template <int N>
__device__ __forceinline__ void cp_wait() {
    asm volatile("cp.async.wait_group %0;" :: "n"(N) : "memory");
}

// ---------------- TF32 tensor-core GEMM: C[M,N] = A[M,K] * B[N,K]^T ----------
// cp.async 3-stage pipeline. 128x128 block tile, BK=32, 256 threads = 8 warps,
// each warp 64x32 (4x2 wmma m16n16k8 tiles). TF32 RN applied in fragments.
#define GSTAGES 3
#define GLDA    36                  // floats per row (32 data + 4 pad), 16B-aligned
#define GMAT_F  (128 * GLDA)        // floats per matrix per stage

__global__ __launch_bounds__(256) void gemm_tf32(
    const float* __restrict__ A, const float* __restrict__ B,
    float* __restrict__ C, int M, int N, int K)
{
    extern __shared__ float sm[];   // [GSTAGES][2][GMAT_F]

    int bm = blockIdx.y * 128;
    int bn = blockIdx.x * 128;
    int tid = threadIdx.x;
    int wid = tid >> 5;
    int wm = wid >> 2;          // 0..1  (64-row strip)
    int wn = wid & 3;           // 0..3  (32-col strip)

    // staging mapping: each thread copies 16 consecutive floats (4 x 16B) per matrix
    int srow = tid >> 1;              // 0..127
    int skc  = (tid & 1) * 16;        // 0 or 16

    const float* Ag = A + (size_t)(bm + srow) * K + skc;
    int brow = bn + srow;
    bool bvalid = brow < N;
    const float* Bg = B + (size_t)(bvalid ? brow : 0) * K + skc;

    unsigned int smem_u32 = (unsigned int)__cvta_generic_to_shared(sm);
    unsigned int stage_elem = (unsigned int)((srow * GLDA + skc) * 4);

    int nk = K >> 5;

    // issue loads for K-step t into stage buffer t % GSTAGES
    auto issue = [&](int t) {
        int buf = t % GSTAGES;
        unsigned int da = smem_u32 + (unsigned int)(buf * 2 * GMAT_F * 4) + stage_elem;
        unsigned int db = da + (unsigned int)(GMAT_F * 4);
        int koff = t * 32;
        #pragma unroll
        for (int v = 0; v < 4; v++) {
            cp_async16(da + v * 16, Ag + koff + v * 4, true);
            cp_async16(db + v * 16, Bg + koff + v * 4, bvalid);
        }
    };

    wmma::fragment<wmma::accumulator, 16, 16, 8, float> acc[4][2];
    #pragma unroll
    for (int i = 0; i < 4; i++)
        #pragma unroll
        for (int j = 0; j < 2; j++)
            wmma::fill_fragment(acc[i][j], 0.0f);

    // prologue: fill GSTAGES-1 stages
    #pragma unroll
    for (int s = 0; s < GSTAGES - 1; s++) { issue(s); cp_commit(); }

    for (int t = 0; t < nk; t++) {
        cp_wait<GSTAGES - 2>();
        __syncthreads();

        // issue next stage (buffer (t + GSTAGES-1) % GSTAGES was drained at iter t-1)
        if (t + GSTAGES - 1 < nk) issue(t + GSTAGES - 1);
        cp_commit();

        int buf = t % GSTAGES;
        const float* Ab = sm + (size_t)buf * 2 * GMAT_F;
        const float* Bb = Ab + GMAT_F;

        #pragma unroll
        for (int ks = 0; ks < 4; ks++) {
            wmma::fragment<wmma::matrix_a, 16, 16, 8, wmma::precision::tf32, wmma::row_major> af[4];
            wmma::fragment<wmma::matrix_b, 16, 16, 8, wmma::precision::tf32, wmma::col_major> bf[2];
            #pragma unroll
            for (int i = 0; i < 4; i++) {
                wmma::load_matrix_sync(af[i], &Ab[(wm * 64 + i * 16) * GLDA + ks * 8], GLDA);
                #pragma unroll
                for (int e = 0; e < af[i].num_elements; e++)
                    af[i].x[e] = to_tf32_rn(af[i].x[e]);
            }
            #pragma unroll
            for (int j = 0; j < 2; j++) {
                wmma::load_matrix_sync(bf[j], &Bb[(wn * 32 + j * 16) * GLDA + ks * 8], GLDA);
                #pragma unroll
                for (int e = 0; e < bf[j].num_elements; e++)
                    bf[j].x[e] = to_tf32_rn(bf[j].x[e]);
            }
            #pragma unroll
            for (int i = 0; i < 4; i++)
                #pragma unroll
                for (int j = 0; j < 2; j++)
                    wmma::mma_sync(acc[i][j], af[i], bf[j], acc[i][j]);
        }
    }

    // epilogue (N columns are multiples of 16 here: 10304, 2048)
    #pragma unroll
    for (int i = 0; i < 4; i++) {
        int r0 = bm + wm * 64 + i * 16;
        #pragma unroll
        for (int j = 0; j < 2; j++) {
            int c0 = bn + wn * 32 + j * 16;
            if (c0 < N)
                wmma::store_matrix_sync(&C[(size_t)r0 * N + c0], acc[i][j], N, wmma::mem_row_major);
        }
    }
}

// ---------------- conv1d (K=4, causal, per-batch padding) + SiLU -------------
__global__ void conv_silu_kernel(const float* __restrict__ cw, const float* __restrict__ cb)
{
    int c = blockIdx.x * 256 + threadIdx.x;
    int t = blockIdx.y;
    if (c >= CONVD) return;
    int pos = t & (LSEQ - 1);
    const float* col = g_zx + INTERN + c;
    float w0 = cw[c*4+0], w1 = cw[c*4+1], w2 = cw[c*4+2], w3 = cw[c*4+3];
    float v = cb[c];
    float x3 = col[(size_t)t * PROJN];
    float x2 = (pos >= 1) ? col[(size_t)(t-1) * PROJN] : 0.f;
    float x1 = (pos >= 2) ? col[(size_t)(t-2) * PROJN] : 0.f;
    float x0 = (pos >= 3) ? col[(size_t)(t-3) * PROJN] : 0.f;
    v += w0*x0 + w1*x1 + w2*x2 + w3*x3;
    g_xbc[(size_t)t * CONVD + c] = v / (1.f + expf(-v));
}

// ---------------- dt: softplus + dA cumsum per chunk -------------------------
__global__ void dt_kernel(const float* __restrict__ dtb, const float* __restrict__ alog)
{
    int bc = blockIdx.x;       // 0..15
    int h = threadIdx.x;       // 0..63
    int t0 = bc * CHUNK;
    float bias = dtb[h];
    float A = -expf(alog[h]);
    float cs = 0.f;
    for (int j = 0; j < CHUNK; j++) {
        int t = t0 + j;
        float raw = g_zx[(size_t)t * PROJN + INTERN + CONVD + h] + bias;
        float dtv = (raw > 20.f) ? raw : log1pf(expf(raw));
        g_dtsp[t * NHEAD + h] = dtv;
        cs += dtv * A;
        g_dacs[t * NHEAD + h] = cs;
    }
}

// ---------------- per-chunk states: S[p,n] = sum_j x[j,p] w[j] B[j,n] --------
__global__ __launch_bounds__(256) void states_kernel()
{
    int h = blockIdx.x, bc = blockIdx.y;
    int g = h >> 3;
    int t0 = bc * CHUNK;
    int tlast = t0 + CHUNK - 1;
    __shared__ float xw[32][64];
    __shared__ float Bs[32][128];
    __shared__ float ws[32];
    int tid = threadIdx.x;
    int tp = tid & 15;     // p block of 4
    int tn = tid >> 4;     // n block of 8
    float acc[4][8];
    #pragma unroll
    for (int i = 0; i < 4; i++)
        #pragma unroll
        for (int k = 0; k < 8; k++) acc[i][k] = 0.f;
    float daL = g_dacs[tlast * NHEAD + h];

    for (int j0 = 0; j0 < CHUNK; j0 += 32) {
        if (tid < 32) {
            int t = t0 + j0 + tid;
            ws[tid] = expf(daL - g_dacs[t * NHEAD + h]) * g_dtsp[t * NHEAD + h];
        }
        __syncthreads();
        for (int e = tid; e < 32*64; e += 256) {
            int j = e >> 6, p = e & 63;
            int t = t0 + j0 + j;
            xw[j][p] = g_xbc[(size_t)t * CONVD + h * HEADP + p] * ws[j];
        }
        for (int e = tid; e < 32*128; e += 256) {
            int j = e >> 7, n = e & 127;
            int t = t0 + j0 + j;
            Bs[j][n] = g_xbc[(size_t)t * CONVD + INTERN + g * NSTATE + n];
        }
        __syncthreads();
        #pragma unroll 4
        for (int j = 0; j < 32; j++) {
            float4 xv = *(const float4*)&xw[j][tp*4];
            float4 b0 = *(const float4*)&Bs[j][tn*8];
            float4 b1 = *(const float4*)&Bs[j][tn*8+4];
            float xr[4] = {xv.x, xv.y, xv.z, xv.w};
            float br[8] = {b0.x,b0.y,b0.z,b0.w,b1.x,b1.y,b1.z,b1.w};
            #pragma unroll
            for (int i = 0; i < 4; i++)
                #pragma unroll
                for (int k = 0; k < 8; k++)
                    acc[i][k] += xr[i] * br[k];
        }
        __syncthreads();
    }
    float* S = g_states + ((size_t)bc * NHEAD + h) * HEADP * NSTATE;
    #pragma unroll
    for (int i = 0; i < 4; i++)
        #pragma unroll
        for (int k = 0; k < 8; k++)
            S[(tp*4 + i) * NSTATE + tn*8 + k] = acc[i][k];
}

// ---------------- inter-chunk scan ------------------------------------------
__global__ void scan_kernel()
{
    int b = blockIdx.x >> 6;
    int h = blockIdx.x & 63;
    for (int e = threadIdx.x; e < HEADP * NSTATE; e += 256) {
        float run = 0.f;
        for (int z = 0; z < NCHUNK; z++) {
            int bc = b * NCHUNK + z;
            size_t off = ((size_t)bc * NHEAD + h) * HEADP * NSTATE + e;
            g_prev[off] = run;
            int tlast = bc * CHUNK + CHUNK - 1;
            float dec = expf(g_dacs[tlast * NHEAD + h]);
            run = dec * run + g_states[off];
        }
    }
}

// ---------------- fused Y_diag + Y_off + D*x ---------------------------------
// block = (itile, h, bc); computes 64 tokens x 64 headdim
__global__ __launch_bounds__(256) void ymain_kernel(const float* __restrict__ Dp)
{
    int it = blockIdx.x, h = blockIdx.y, bc = blockIdx.z;
    int g = h >> 3;
    int t0 = bc * CHUNK;
    int i0 = it * 64;
    extern __shared__ float sm[];
    float* Cs  = sm;             // [64][129]
    float* Js  = Cs + 64*129;    // [64][129]  (prev or B_j)
    float* Xs  = Js + 64*129;    // [64][65]
    float* Ss  = Xs + 64*65;     // [64][65]
    float* dai = Ss + 64*65;     // [64]
    float* eiv = dai + 64;       // [64]
    float* daj = eiv + 64;       // [64]
    float* dtj = daj + 64;       // [64]

    int tid = threadIdx.x;
    int tx = tid & 15, ty = tid >> 4;

    // load C_i tile and dA_cs for i-rows
    for (int e = tid; e < 64*128; e += 256) {
        int i = e >> 7, n = e & 127;
        Cs[i*129 + n] = g_xbc[(size_t)(t0 + i0 + i) * CONVD + INTERN + NGRP*NSTATE + g*NSTATE + n];
    }
    if (tid < 64) {
        float d = g_dacs[(t0 + i0 + tid) * NHEAD + h];
        dai[tid] = d;
        eiv[tid] = expf(d);
    }
    // load prev state [p][n]
    const float* prev = g_prev + ((size_t)bc * NHEAD + h) * HEADP * NSTATE;
    for (int e = tid; e < 64*128; e += 256) {
        int p = e >> 7, n = e & 127;
        Js[p*129 + n] = prev[p * NSTATE + n];
    }
    __syncthreads();

    // Y_off: acc[i][p] = ei[i] * sum_n C[i,n]*prev[p,n]
    float acc[4][4];
    {
        float off[4][4];
        #pragma unroll
        for (int i = 0; i < 4; i++)
            #pragma unroll
            for (int p = 0; p < 4; p++) off[i][p] = 0.f;
        #pragma unroll 4
        for (int n = 0; n < 128; n++) {
            float a[4], bv[4];
            #pragma unroll
            for (int i = 0; i < 4; i++) a[i] = Cs[(ty*4 + i)*129 + n];
            #pragma unroll
            for (int p = 0; p < 4; p++) bv[p] = Js[(tx*4 + p)*129 + n];
            #pragma unroll
            for (int i = 0; i < 4; i++)
                #pragma unroll
                for (int p = 0; p < 4; p++) off[i][p] += a[i] * bv[p];
        }
        #pragma unroll
        for (int i = 0; i < 4; i++)
            #pragma unroll
            for (int p = 0; p < 4; p++) acc[i][p] = off[i][p] * eiv[ty*4 + i];
    }
    __syncthreads();

    // Y_diag: loop over j-tiles <= i-tile
    for (int jt = 0; jt <= it; jt++) {
        int j0 = jt * 64;
        for (int e = tid; e < 64*128; e += 256) {
            int j = e >> 7, n = e & 127;
            Js[j*129 + n] = g_xbc[(size_t)(t0 + j0 + j) * CONVD + INTERN + g*NSTATE + n];
        }
        for (int e = tid; e < 64*64; e += 256) {
            int j = e >> 6, p = e & 63;
            Xs[j*65 + p] = g_xbc[(size_t)(t0 + j0 + j) * CONVD + h * HEADP + p];
        }
        if (tid < 64) {
            int t = t0 + j0 + tid;
            daj[tid] = g_dacs[t * NHEAD + h];
            dtj[tid] = g_dtsp[t * NHEAD + h];
        }
        __syncthreads();

        // S = C_i . B_j^T over N=128
        float s[4][4];
        #pragma unroll
        for (int i = 0; i < 4; i++)
            #pragma unroll
            for (int j = 0; j < 4; j++) s[i][j] = 0.f;
        #pragma unroll 4
        for (int n = 0; n < 128; n++) {
            float a[4], bv[4];
            #pragma unroll
            for (int i = 0; i < 4; i++) a[i] = Cs[(ty*4 + i)*129 + n];
            #pragma unroll
            for (int j = 0; j < 4; j++) bv[j] = Js[(tx*4 + j)*129 + n];
            #pragma unroll
            for (int i = 0; i < 4; i++)
                #pragma unroll
                for (int j = 0; j < 4; j++) s[i][j] += a[i] * bv[j];
        }
        // mask + decay + dt, stage to smem
        #pragma unroll
        for (int ii = 0; ii < 4; ii++) {
            int il = ty*4 + ii;
            int ig = i0 + il;
            #pragma unroll
            for (int jj = 0; jj < 4; jj++) {
                int jl = tx*4 + jj;
                int jg = j0 + jl;
                float v = 0.f;
                if (ig >= jg) v = s[ii][jj] * expf(dai[il] - daj[jl]) * dtj[jl];
                Ss[il*65 + jl] = v;
            }
        }
        __syncthreads();
        // acc += S @ x_j
        #pragma unroll 4
        for (int j = 0; j < 64; j++) {
            float a[4], bv[4];
            #pragma unroll
            for (int i = 0; i < 4; i++) a[i] = Ss[(ty*4 + i)*65 + j];
            #pragma unroll
            for (int p = 0; p < 4; p++) bv[p] = Xs[j*65 + tx*4 + p];
            #pragma unroll
            for (int i = 0; i < 4; i++)
                #pragma unroll
                for (int p = 0; p < 4; p++) acc[i][p] += a[i] * bv[p];
        }
        __syncthreads();
    }

    // epilogue: + D[h] * x_i ; write y
    float Dh = Dp[h];
    #pragma unroll
    for (int ii = 0; ii < 4; ii++) {
        int t = t0 + i0 + ty*4 + ii;
        #pragma unroll
        for (int pp = 0; pp < 4; pp++) {
            int p = tx*4 + pp;
            float xv = g_xbc[(size_t)t * CONVD + h * HEADP + p];
            g_y[(size_t)t * INTERN + h * HEADP + p] = acc[ii][pp] + Dh * xv;
        }
    }
}

// ---------------- RMS norm + silu(z) gate (in-place on g_y) ------------------
__global__ void normgate_kernel(const float* __restrict__ nw)
{
    int t = blockIdx.x;
    float s = 0.f;
    for (int c = threadIdx.x; c < INTERN; c += 256) {
        float v = g_y[(size_t)t * INTERN + c];
        s += v * v;
    }
    __shared__ float red[8];
    #pragma unroll
    for (int o = 16; o; o >>= 1) s += __shfl_xor_sync(0xffffffffu, s, o);
    if ((threadIdx.x & 31) == 0) red[threadIdx.x >> 5] = s;
    __syncthreads();
    if (threadIdx.x < 8) {
        float v = red[threadIdx.x];
        #pragma unroll
        for (int o = 4; o; o >>= 1) v += __shfl_xor_sync(0xffu, v, o);
        if (threadIdx.x == 0) red[0] = v;
    }
    __syncthreads();
    float inv = rsqrtf(red[0] / (float)INTERN + EPSV);
    for (int c = threadIdx.x; c < INTERN; c += 256) {
        float v = g_y[(size_t)t * INTERN + c] * inv * nw[c];
        float z = g_zx[(size_t)t * PROJN + c];
        g_y[(size_t)t * INTERN + c] = v * (z / (1.f + expf(-z)));
    }
}

// ---------------- launch ------------------------------------------------------
extern "C" void kernel_launch(void* const* d_in, const int* in_sizes, int n_in,
                              void* d_out, int out_size)
{
    const float* hs    = (const float*)d_in[0];
    const float* w_in  = (const float*)d_in[1];
    const float* cw    = (const float*)d_in[2];
    const float* cb    = (const float*)d_in[3];
    const float* dtb   = (const float*)d_in[4];
    const float* alog  = (const float*)d_in[5];
    const float* Dp    = (const float*)d_in[6];
    const float* nw    = (const float*)d_in[7];
    const float* w_out = (const float*)d_in[8];
    float* out = (float*)d_out;

    float *zx, *y;
    cudaGetSymbolAddress((void**)&zx, g_zx);
    cudaGetSymbolAddress((void**)&y, g_y);

    size_t gsmem = (size_t)GSTAGES * 2 * GMAT_F * sizeof(float);   // 3 stages x (A+B)
    cudaFuncSetAttribute(gemm_tf32, cudaFuncAttributeMaxDynamicSharedMemorySize, (int)gsmem);

    size_t ysmem = (size_t)(64*129*2 + 64*65*2 + 4*64) * sizeof(float);
    cudaFuncSetAttribute(ymain_kernel, cudaFuncAttributeMaxDynamicSharedMemorySize, (int)ysmem);

    // 1) in_proj GEMM: [4096,10304] = [4096,2048] x [10304,2048]^T  (tf32 TC)
    gemm_tf32<<<dim3((PROJN + 127) / 128, BT / 128), 256, gsmem>>>(hs, w_in, zx, BT, PROJN, HIDN);
    // 2) conv + silu
    conv_silu_kernel<<<dim3(CONVD / 256, BT), 256>>>(cw, cb);
    // 3) dt softplus + dA cumsum
    dt_kernel<<<NBC, NHEAD>>>(dtb, alog);
    // 4) per-chunk states
    states_kernel<<<dim3(NHEAD, NBC), 256>>>();
    // 5) inter-chunk scan
    scan_kernel<<<NBATCH * NHEAD, 256>>>();
    // 6) fused diag + off + D*x
    ymain_kernel<<<dim3(CHUNK / 64, NHEAD, NBC), 256, ysmem>>>(Dp);
    // 7) rmsnorm + gate
    normgate_kernel<<<BT, 256>>>(nw);
    // 8) out_proj GEMM: [4096,2048] = [4096,4096] x [2048,4096]^T  (tf32 TC)
    gemm_tf32<<<dim3(HIDN / 128, BT / 128), 256, gsmem>>>(y, w_out, out, BT, HIDN, INTERN);
}

// round 14
// speedup vs baseline: 1.1283x; 1.0769x over previous
#include <cuda_runtime.h>
#include <mma.h>
#include <math.h>
#include <cstdint>
#include <stdint.h>

using namespace nvcuda;

#define HIDN   2048
#define INTERN 4096
#define CONVD  6144
#define PROJN  10304
#define NHEAD  64
#define HEADP  64
#define NGRP   8
#define NSTATE 128
#define CHUNK  256
#define LSEQ   2048
#define NBATCH 2
#define NCHUNK 8
#define BT     4096          // total tokens
#define NBC    16            // NBATCH*NCHUNK
#define EPSV   1e-5f

// ---------------- scratch (device globals; no allocation) ----------------
__device__ float g_zx[(size_t)BT * PROJN];        // in_proj output
__device__ float g_xbc[(size_t)BT * CONVD];       // conv+silu output
__device__ float g_dtsp[BT * NHEAD];              // softplus(dt)
__device__ float g_dacs[BT * NHEAD];              // cumsum(dt*A) per chunk
__device__ float g_states[(size_t)NBC * NHEAD * HEADP * NSTATE];
__device__ float g_prev[(size_t)NBC * NHEAD * HEADP * NSTATE];
__device__ float g_y[(size_t)BT * INTERN];
// pre-rounded (tf32) GEMM operands
__device__ float g_ar[(size_t)BT * HIDN];         // hs rounded
__device__ float g_br[(size_t)PROJN * HIDN];      // in_proj_w rounded
__device__ float g_cr[(size_t)HIDN * INTERN];     // out_proj_w rounded

__device__ __forceinline__ float to_tf32_rn(float x) {
    float r;
    asm("cvt.rna.tf32.f32 %0, %1;" : "=f"(r) : "f"(x));
    return r;
}

// ---------------- pre-round: out[i] = tf32_rn(in[i]), float4 grid-stride ----
__global__ void round_tf32_kernel(const float* __restrict__ in, float* __restrict__ out, int n4)
{
    int i = blockIdx.x * blockDim.x + threadIdx.x;
    int stride = gridDim.x * blockDim.x;
    for (; i < n4; i += stride) {
        float4 v = ((const float4*)in)[i];
        v.x = to_tf32_rn(v.x); v.y = to_tf32_rn(v.y);
        v.z = to_tf32_rn(v.z); v.w = to_tf32_rn(v.w);
        ((float4*)out)[i] = v;
    }
}

// ---------------- TF32 tensor-core GEMM: C[M,N] = A[M,K] * B[N,K]^T ----------
// Inputs are PRE-ROUNDED to tf32. 128x128 tile, BK=32, 256 threads = 8 warps,
// each warp 64x32 (4x2 wmma m16n16k8 tiles). Pure float4 copy staging.
#define LDA 40

__global__ __launch_bounds__(256) void gemm_tf32(
    const float* __restrict__ A, const float* __restrict__ B,
    float* __restrict__ C, int M, int N, int K)
{
    __shared__ float As[128 * LDA];
    __shared__ float Bs[128 * LDA];

    int bm = blockIdx.y * 128;
    int bn = blockIdx.x * 128;
    int tid = threadIdx.x;
    int wid = tid >> 5;
    int wm = wid >> 2;          // 0..1  (64-row strip)
    int wn = wid & 3;           // 0..3  (32-col strip)

    // staging mapping: each thread copies 16 consecutive floats (4 x float4)
    int srow = tid >> 1;              // 0..127
    int skc  = (tid & 1) * 16;        // 0 or 16

    const float* Ag = A + (size_t)(bm + srow) * K + skc;
    int brow = bn + srow;
    bool bvalid = brow < N;
    const float* Bg = B + (size_t)(bvalid ? brow : 0) * K + skc;

    wmma::fragment<wmma::accumulator, 16, 16, 8, float> acc[4][2];
    #pragma unroll
    for (int i = 0; i < 4; i++)
        #pragma unroll
        for (int j = 0; j < 2; j++)
            wmma::fill_fragment(acc[i][j], 0.0f);

    for (int k0 = 0; k0 < K; k0 += 32) {
        #pragma unroll
        for (int v = 0; v < 4; v++) {
            float4 a = *(const float4*)(Ag + k0 + v * 4);
            *(float4*)&As[srow * LDA + skc + v * 4] = a;
            float4 b = bvalid ? *(const float4*)(Bg + k0 + v * 4)
                              : make_float4(0.f, 0.f, 0.f, 0.f);
            *(float4*)&Bs[srow * LDA + skc + v * 4] = b;
        }
        __syncthreads();

        #pragma unroll
        for (int ks = 0; ks < 4; ks++) {
            wmma::fragment<wmma::matrix_a, 16, 16, 8, wmma::precision::tf32, wmma::row_major> af[4];
            wmma::fragment<wmma::matrix_b, 16, 16, 8, wmma::precision::tf32, wmma::col_major> bf[2];
            #pragma unroll
            for (int i = 0; i < 4; i++)
                wmma::load_matrix_sync(af[i], &As[(wm * 64 + i * 16) * LDA + ks * 8], LDA);
            #pragma unroll
            for (int j = 0; j < 2; j++)
                wmma::load_matrix_sync(bf[j], &Bs[(wn * 32 + j * 16) * LDA + ks * 8], LDA);
            #pragma unroll
            for (int i = 0; i < 4; i++)
                #pragma unroll
                for (int j = 0; j < 2; j++)
                    wmma::mma_sync(acc[i][j], af[i], bf[j], acc[i][j]);
        }
        __syncthreads();
    }

    // epilogue (N is always a multiple of 16 here: 10304, 2048)
    #pragma unroll
    for (int i = 0; i < 4; i++) {
        int r0 = bm + wm * 64 + i * 16;
        #pragma unroll
        for (int j = 0; j < 2; j++) {
            int c0 = bn + wn * 32 + j * 16;
            if (c0 < N)
                wmma::store_matrix_sync(&C[(size_t)r0 * N + c0], acc[i][j], N, wmma::mem_row_major);
        }
    }
}

// ---------------- conv1d (K=4, causal, per-batch padding) + SiLU -------------
__global__ void conv_silu_kernel(const float* __restrict__ cw, const float* __restrict__ cb)
{
    int c = blockIdx.x * 256 + threadIdx.x;
    int t = blockIdx.y;
    if (c >= CONVD) return;
    int pos = t & (LSEQ - 1);
    const float* col = g_zx + INTERN + c;
    float w0 = cw[c*4+0], w1 = cw[c*4+1], w2 = cw[c*4+2], w3 = cw[c*4+3];
    float v = cb[c];
    float x3 = col[(size_t)t * PROJN];
    float x2 = (pos >= 1) ? col[(size_t)(t-1) * PROJN] : 0.f;
    float x1 = (pos >= 2) ? col[(size_t)(t-2) * PROJN] : 0.f;
    float x0 = (pos >= 3) ? col[(size_t)(t-3) * PROJN] : 0.f;
    v += w0*x0 + w1*x1 + w2*x2 + w3*x3;
    g_xbc[(size_t)t * CONVD + c] = v / (1.f + expf(-v));
}

// ---------------- dt: softplus + dA cumsum per chunk -------------------------
__global__ void dt_kernel(const float* __restrict__ dtb, const float* __restrict__ alog)
{
    int bc = blockIdx.x;       // 0..15
    int h = threadIdx.x;       // 0..63
    int t0 = bc * CHUNK;
    float bias = dtb[h];
    float A = -expf(alog[h]);
    float cs = 0.f;
    for (int j = 0; j < CHUNK; j++) {
        int t = t0 + j;
        float raw = g_zx[(size_t)t * PROJN + INTERN + CONVD + h] + bias;
        float dtv = (raw > 20.f) ? raw : log1pf(expf(raw));
        g_dtsp[t * NHEAD + h] = dtv;
        cs += dtv * A;
        g_dacs[t * NHEAD + h] = cs;
    }
}

// ---------------- per-chunk states: S[p,n] = sum_j x[j,p] w[j] B[j,n] --------
__global__ __launch_bounds__(256) void states_kernel()
{
    int h = blockIdx.x, bc = blockIdx.y;
    int g = h >> 3;
    int t0 = bc * CHUNK;
    int tlast = t0 + CHUNK - 1;
    __shared__ float xw[32][64];
    __shared__ float Bs[32][128];
    __shared__ float ws[32];
    int tid = threadIdx.x;
    int tp = tid & 15;     // p block of 4
    int tn = tid >> 4;     // n block of 8
    float acc[4][8];
    #pragma unroll
    for (int i = 0; i < 4; i++)
        #pragma unroll
        for (int k = 0; k < 8; k++) acc[i][k] = 0.f;
    float daL = g_dacs[tlast * NHEAD + h];

    for (int j0 = 0; j0 < CHUNK; j0 += 32) {
        if (tid < 32) {
            int t = t0 + j0 + tid;
            ws[tid] = expf(daL - g_dacs[t * NHEAD + h]) * g_dtsp[t * NHEAD + h];
        }
        __syncthreads();
        for (int e = tid; e < 32*64; e += 256) {
            int j = e >> 6, p = e & 63;
            int t = t0 + j0 + j;
            xw[j][p] = g_xbc[(size_t)t * CONVD + h * HEADP + p] * ws[j];
        }
        for (int e = tid; e < 32*128; e += 256) {
            int j = e >> 7, n = e & 127;
            int t = t0 + j0 + j;
            Bs[j][n] = g_xbc[(size_t)t * CONVD + INTERN + g * NSTATE + n];
        }
        __syncthreads();
        #pragma unroll 4
        for (int j = 0; j < 32; j++) {
            float4 xv = *(const float4*)&xw[j][tp*4];
            float4 b0 = *(const float4*)&Bs[j][tn*8];
            float4 b1 = *(const float4*)&Bs[j][tn*8+4];
            float xr[4] = {xv.x, xv.y, xv.z, xv.w};
            float br[8] = {b0.x,b0.y,b0.z,b0.w,b1.x,b1.y,b1.z,b1.w};
            #pragma unroll
            for (int i = 0; i < 4; i++)
                #pragma unroll
                for (int k = 0; k < 8; k++)
                    acc[i][k] += xr[i] * br[k];
        }
        __syncthreads();
    }
    float* S = g_states + ((size_t)bc * NHEAD + h) * HEADP * NSTATE;
    #pragma unroll
    for (int i = 0; i < 4; i++)
        #pragma unroll
        for (int k = 0; k < 8; k++)
            S[(tp*4 + i) * NSTATE + tn*8 + k] = acc[i][k];
}

// ---------------- inter-chunk scan ------------------------------------------
__global__ void scan_kernel()
{
    int b = blockIdx.x >> 6;
    int h = blockIdx.x & 63;
    for (int e = threadIdx.x; e < HEADP * NSTATE; e += 256) {
        float run = 0.f;
        for (int z = 0; z < NCHUNK; z++) {
            int bc = b * NCHUNK + z;
            size_t off = ((size_t)bc * NHEAD + h) * HEADP * NSTATE + e;
            g_prev[off] = run;
            int tlast = bc * CHUNK + CHUNK - 1;
            float dec = expf(g_dacs[tlast * NHEAD + h]);
            run = dec * run + g_states[off];
        }
    }
}

// ---------------- fused Y_diag + Y_off + D*x ---------------------------------
// block = (itile, h, bc); computes 64 tokens x 64 headdim
__global__ __launch_bounds__(256) void ymain_kernel(const float* __restrict__ Dp)
{
    int it = blockIdx.x, h = blockIdx.y, bc = blockIdx.z;
    int g = h >> 3;
    int t0 = bc * CHUNK;
    int i0 = it * 64;
    extern __shared__ float sm[];
    float* Cs  = sm;             // [64][129]
    float* Js  = Cs + 64*129;    // [64][129]  (prev or B_j)
    float* Xs  = Js + 64*129;    // [64][65]
    float* Ss  = Xs + 64*65;     // [64][65]
    float* dai = Ss + 64*65;     // [64]
    float* eiv = dai + 64;       // [64]
    float* daj = eiv + 64;       // [64]
    float* dtj = daj + 64;       // [64]

    int tid = threadIdx.x;
    int tx = tid & 15, ty = tid >> 4;

    // load C_i tile and dA_cs for i-rows
    for (int e = tid; e < 64*128; e += 256) {
        int i = e >> 7, n = e & 127;
        Cs[i*129 + n] = g_xbc[(size_t)(t0 + i0 + i) * CONVD + INTERN + NGRP*NSTATE + g*NSTATE + n];
    }
    if (tid < 64) {
        float d = g_dacs[(t0 + i0 + tid) * NHEAD + h];
        dai[tid] = d;
        eiv[tid] = expf(d);
    }
    // load prev state [p][n]
    const float* prev = g_prev + ((size_t)bc * NHEAD + h) * HEADP * NSTATE;
    for (int e = tid; e < 64*128; e += 256) {
        int p = e >> 7, n = e & 127;
        Js[p*129 + n] = prev[p * NSTATE + n];
    }
    __syncthreads();

    // Y_off: acc[i][p] = ei[i] * sum_n C[i,n]*prev[p,n]
    float acc[4][4];
    {
        float off[4][4];
        #pragma unroll
        for (int i = 0; i < 4; i++)
            #pragma unroll
            for (int p = 0; p < 4; p++) off[i][p] = 0.f;
        #pragma unroll 4
        for (int n = 0; n < 128; n++) {
            float a[4], bv[4];
            #pragma unroll
            for (int i = 0; i < 4; i++) a[i] = Cs[(ty*4 + i)*129 + n];
            #pragma unroll
            for (int p = 0; p < 4; p++) bv[p] = Js[(tx*4 + p)*129 + n];
            #pragma unroll
            for (int i = 0; i < 4; i++)
                #pragma unroll
                for (int p = 0; p < 4; p++) off[i][p] += a[i] * bv[p];
        }
        #pragma unroll
        for (int i = 0; i < 4; i++)
            #pragma unroll
            for (int p = 0; p < 4; p++) acc[i][p] = off[i][p] * eiv[ty*4 + i];
    }
    __syncthreads();

    // Y_diag: loop over j-tiles <= i-tile
    for (int jt = 0; jt <= it; jt++) {
        int j0 = jt * 64;
        for (int e = tid; e < 64*128; e += 256) {
            int j = e >> 7, n = e & 127;
            Js[j*129 + n] = g_xbc[(size_t)(t0 + j0 + j) * CONVD + INTERN + g*NSTATE + n];
        }
        for (int e = tid; e < 64*64; e += 256) {
            int j = e >> 6, p = e & 63;
            Xs[j*65 + p] = g_xbc[(size_t)(t0 + j0 + j) * CONVD + h * HEADP + p];
        }
        if (tid < 64) {
            int t = t0 + j0 + tid;
            daj[tid] = g_dacs[t * NHEAD + h];
            dtj[tid] = g_dtsp[t * NHEAD + h];
        }
        __syncthreads();

        // S = C_i . B_j^T over N=128
        float s[4][4];
        #pragma unroll
        for (int i = 0; i < 4; i++)
            #pragma unroll
            for (int j = 0; j < 4; j++) s[i][j] = 0.f;
        #pragma unroll 4
        for (int n = 0; n < 128; n++) {
            float a[4], bv[4];
            #pragma unroll
            for (int i = 0; i < 4; i++) a[i] = Cs[(ty*4 + i)*129 + n];
            #pragma unroll
            for (int j = 0; j < 4; j++) bv[j] = Js[(tx*4 + j)*129 + n];
            #pragma unroll
            for (int i = 0; i < 4; i++)
                #pragma unroll
                for (int j = 0; j < 4; j++) s[i][j] += a[i] * bv[j];
        }
        // mask + decay + dt, stage to smem
        #pragma unroll
        for (int ii = 0; ii < 4; ii++) {
            int il = ty*4 + ii;
            int ig = i0 + il;
            #pragma unroll
            for (int jj = 0; jj < 4; jj++) {
                int jl = tx*4 + jj;
                int jg = j0 + jl;
                float v = 0.f;
                if (ig >= jg) v = s[ii][jj] * expf(dai[il] - daj[jl]) * dtj[jl];
                Ss[il*65 + jl] = v;
            }
        }
        __syncthreads();
        // acc += S @ x_j
        #pragma unroll 4
        for (int j = 0; j < 64; j++) {
            float a[4], bv[4];
            #pragma unroll
            for (int i = 0; i < 4; i++) a[i] = Ss[(ty*4 + i)*65 + j];
            #pragma unroll
            for (int p = 0; p < 4; p++) bv[p] = Xs[j*65 + tx*4 + p];
            #pragma unroll
            for (int i = 0; i < 4; i++)
                #pragma unroll
                for (int p = 0; p < 4; p++) acc[i][p] += a[i] * bv[p];
        }
        __syncthreads();
    }

    // epilogue: + D[h] * x_i ; write y
    float Dh = Dp[h];
    #pragma unroll
    for (int ii = 0; ii < 4; ii++) {
        int t = t0 + i0 + ty*4 + ii;
        #pragma unroll
        for (int pp = 0; pp < 4; pp++) {
            int p = tx*4 + pp;
            float xv = g_xbc[(size_t)t * CONVD + h * HEADP + p];
            g_y[(size_t)t * INTERN + h * HEADP + p] = acc[ii][pp] + Dh * xv;
        }
    }
}

// ---------------- RMS norm + silu(z) gate (in-place, tf32-rounded output) ----
__global__ void normgate_kernel(const float* __restrict__ nw)
{
    int t = blockIdx.x;
    float s = 0.f;
    for (int c = threadIdx.x; c < INTERN; c += 256) {
        float v = g_y[(size_t)t * INTERN + c];
        s += v * v;
    }
    __shared__ float red[8];
    #pragma unroll
    for (int o = 16; o; o >>= 1) s += __shfl_xor_sync(0xffffffffu, s, o);
    if ((threadIdx.x & 31) == 0) red[threadIdx.x >> 5] = s;
    __syncthreads();
    if (threadIdx.x < 8) {
        float v = red[threadIdx.x];
        #pragma unroll
        for (int o = 4; o; o >>= 1) v += __shfl_xor_sync(0xffu, v, o);
        if (threadIdx.x == 0) red[0] = v;
    }
    __syncthreads();
    float inv = rsqrtf(red[0] / (float)INTERN + EPSV);
    for (int c = threadIdx.x; c < INTERN; c += 256) {
        float v = g_y[(size_t)t * INTERN + c] * inv * nw[c];
        float z = g_zx[(size_t)t * PROJN + c];
        // pre-round for GEMM2 (same value the stage-time cvt would produce)
        g_y[(size_t)t * INTERN + c] = to_tf32_rn(v * (z / (1.f + expf(-z))));
    }
}

// ---------------- launch ------------------------------------------------------
extern "C" void kernel_launch(void* const* d_in, const int* in_sizes, int n_in,
                              void* d_out, int out_size)
{
    const float* hs    = (const float*)d_in[0];
    const float* w_in  = (const float*)d_in[1];
    const float* cw    = (const float*)d_in[2];
    const float* cb    = (const float*)d_in[3];
    const float* dtb   = (const float*)d_in[4];
    const float* alog  = (const float*)d_in[5];
    const float* Dp    = (const float*)d_in[6];
    const float* nw    = (const float*)d_in[7];
    const float* w_out = (const float*)d_in[8];
    float* out = (float*)d_out;

    float *zx, *y, *ar, *br, *cr;
    cudaGetSymbolAddress((void**)&zx, g_zx);
    cudaGetSymbolAddress((void**)&y, g_y);
    cudaGetSymbolAddress((void**)&ar, g_ar);
    cudaGetSymbolAddress((void**)&br, g_br);
    cudaGetSymbolAddress((void**)&cr, g_cr);

    size_t ysmem = (size_t)(64*129*2 + 64*65*2 + 4*64) * sizeof(float);
    cudaFuncSetAttribute(ymain_kernel, cudaFuncAttributeMaxDynamicSharedMemorySize, (int)ysmem);

    // 0) pre-round GEMM operands to tf32 (bitwise same as stage-time rounding)
    round_tf32_kernel<<<2048, 256>>>(hs,    ar, (BT * HIDN) / 4);
    round_tf32_kernel<<<2048, 256>>>(w_in,  br, (PROJN * HIDN) / 4);
    round_tf32_kernel<<<2048, 256>>>(w_out, cr, (HIDN * INTERN) / 4);

    // 1) in_proj GEMM: [4096,10304] = [4096,2048] x [10304,2048]^T  (tf32 TC)
    gemm_tf32<<<dim3((PROJN + 127) / 128, BT / 128), 256>>>(ar, br, zx, BT, PROJN, HIDN);
    // 2) conv + silu
    conv_silu_kernel<<<dim3(CONVD / 256, BT), 256>>>(cw, cb);
    // 3) dt softplus + dA cumsum
    dt_kernel<<<NBC, NHEAD>>>(dtb, alog);
    // 4) per-chunk states
    states_kernel<<<dim3(NHEAD, NBC), 256>>>();
    // 5) inter-chunk scan
    scan_kernel<<<NBATCH * NHEAD, 256>>>();
    // 6) fused diag + off + D*x
    ymain_kernel<<<dim3(CHUNK / 64, NHEAD, NBC), 256, ysmem>>>(Dp);
    // 7) rmsnorm + gate (writes tf32-rounded y)
    normgate_kernel<<<BT, 256>>>(nw);
    // 8) out_proj GEMM: [4096,2048] = [4096,4096] x [2048,4096]^T  (tf32 TC)
    gemm_tf32<<<dim3(HIDN / 128, BT / 128), 256>>>(y, cr, out, BT, HIDN, INTERN);
}

// round 15
// speedup vs baseline: 1.1452x; 1.0150x over previous
#include <cuda_runtime.h>
#include <mma.h>
#include <math.h>
#include <cstdint>
#include <stdint.h>

using namespace nvcuda;

#define HIDN   2048
#define INTERN 4096
#define CONVD  6144
#define PROJN  10304
#define NHEAD  64
#define HEADP  64
#define NGRP   8
#define NSTATE 128
#define CHUNK  256
#define LSEQ   2048
#define NBATCH 2
#define NCHUNK 8
#define BT     4096          // total tokens
#define NBC    16            // NBATCH*NCHUNK
#define EPSV   1e-5f

// ---------------- scratch (device globals; no allocation) ----------------
__device__ float g_zx[(size_t)BT * PROJN];        // in_proj output
__device__ float g_xbc[(size_t)BT * CONVD];       // conv+silu output
__device__ float g_dtsp[BT * NHEAD];              // softplus(dt)
__device__ float g_dacs[BT * NHEAD];              // cumsum(dt*A) per chunk
__device__ float g_states[(size_t)NBC * NHEAD * HEADP * NSTATE];
__device__ float g_prev[(size_t)NBC * NHEAD * HEADP * NSTATE];
__device__ float g_y[(size_t)BT * INTERN];
// pre-rounded (tf32) GEMM operands
__device__ float g_ar[(size_t)BT * HIDN];         // hs rounded
__device__ float g_br[(size_t)PROJN * HIDN];      // in_proj_w rounded
__device__ float g_cr[(size_t)HIDN * INTERN];     // out_proj_w rounded

__device__ __forceinline__ float to_tf32_rn(float x) {
    float r;
    asm("cvt.rna.tf32.f32 %0, %1;" : "=f"(r) : "f"(x));
    return r;
}

__device__ __forceinline__ void cp_async16(unsigned int saddr, const void* gptr, bool pred) {
    int sz = pred ? 16 : 0;
    asm volatile("cp.async.cg.shared.global [%0], [%1], 16, %2;"
                 :: "r"(saddr), "l"(gptr), "r"(sz) : "memory");
}
__device__ __forceinline__ void cp_commit() {
    asm volatile("cp.async.commit_group;" ::: "memory");
}
template <int N>
__device__ __forceinline__ void cp_wait() {
    asm volatile("cp.async.wait_group %0;" :: "n"(N) : "memory");
}

// ---------------- pre-round: out[i] = tf32_rn(in[i]), float4 grid-stride ----
__global__ void round_tf32_kernel(const float* __restrict__ in, float* __restrict__ out, int n4)
{
    int i = blockIdx.x * blockDim.x + threadIdx.x;
    int stride = gridDim.x * blockDim.x;
    for (; i < n4; i += stride) {
        float4 v = ((const float4*)in)[i];
        v.x = to_tf32_rn(v.x); v.y = to_tf32_rn(v.y);
        v.z = to_tf32_rn(v.z); v.w = to_tf32_rn(v.w);
        ((float4*)out)[i] = v;
    }
}

// ---------------- TF32 tensor-core GEMM: C[M,N] = A[M,K] * B[N,K]^T ----------
// Pre-rounded inputs. cp.async DOUBLE buffer (2 stages) at 2 CTAs/SM.
// 128x128 tile, BK=32, 256 threads = 8 warps, each warp 64x32 (4x2 wmma tiles).
#define LDA 40
#define STG_F (2 * 128 * LDA)        // floats per stage (A + B)
#define GSMEM (2 * STG_F * 4)        // bytes, 2 stages = 80 KB

__global__ __launch_bounds__(256, 2) void gemm_tf32(
    const float* __restrict__ A, const float* __restrict__ B,
    float* __restrict__ C, int M, int N, int K)
{
    extern __shared__ float sm[];    // [2][A:128*LDA | B:128*LDA]

    int bm = blockIdx.y * 128;
    int bn = blockIdx.x * 128;
    int tid = threadIdx.x;
    int wid = tid >> 5;
    int wm = wid >> 2;          // 0..1  (64-row strip)
    int wn = wid & 3;           // 0..3  (32-col strip)

    // staging mapping: each thread copies 16 consecutive floats (4 x 16B) per matrix
    int srow = tid >> 1;              // 0..127
    int skc  = (tid & 1) * 16;        // 0 or 16

    const float* Ag = A + (size_t)(bm + srow) * K + skc;
    int brow = bn + srow;
    bool bvalid = brow < N;
    const float* Bg = B + (size_t)(bvalid ? brow : 0) * K + skc;

    unsigned int smem_u32 = (unsigned int)__cvta_generic_to_shared(sm);
    unsigned int off_elem = (unsigned int)((srow * LDA + skc) * 4);

    int nk = K >> 5;

    auto issue = [&](int t) {
        int buf = t & 1;
        unsigned int da = smem_u32 + (unsigned int)(buf * STG_F * 4) + off_elem;
        unsigned int db = da + (unsigned int)(128 * LDA * 4);
        int koff = t * 32;
        #pragma unroll
        for (int v = 0; v < 4; v++) {
            cp_async16(da + v * 16, Ag + koff + v * 4, true);
            cp_async16(db + v * 16, Bg + koff + v * 4, bvalid);
        }
    };

    wmma::fragment<wmma::accumulator, 16, 16, 8, float> acc[4][2];
    #pragma unroll
    for (int i = 0; i < 4; i++)
        #pragma unroll
        for (int j = 0; j < 2; j++)
            wmma::fill_fragment(acc[i][j], 0.0f);

    issue(0); cp_commit();

    for (int t = 0; t < nk; t++) {
        cp_wait<0>();
        __syncthreads();                 // stage t visible; prior compute done

        if (t + 1 < nk) { issue(t + 1); cp_commit(); }   // overlap with compute

        const float* Ab = sm + (size_t)(t & 1) * STG_F;
        const float* Bb = Ab + 128 * LDA;

        #pragma unroll
        for (int ks = 0; ks < 4; ks++) {
            wmma::fragment<wmma::matrix_a, 16, 16, 8, wmma::precision::tf32, wmma::row_major> af[4];
            wmma::fragment<wmma::matrix_b, 16, 16, 8, wmma::precision::tf32, wmma::col_major> bf[2];
            #pragma unroll
            for (int i = 0; i < 4; i++)
                wmma::load_matrix_sync(af[i], &Ab[(wm * 64 + i * 16) * LDA + ks * 8], LDA);
            #pragma unroll
            for (int j = 0; j < 2; j++)
                wmma::load_matrix_sync(bf[j], &Bb[(wn * 32 + j * 16) * LDA + ks * 8], LDA);
            #pragma unroll
            for (int i = 0; i < 4; i++)
                #pragma unroll
                for (int j = 0; j < 2; j++)
                    wmma::mma_sync(acc[i][j], af[i], bf[j], acc[i][j]);
        }
    }

    // epilogue (N is always a multiple of 16 here: 10304, 2048)
    #pragma unroll
    for (int i = 0; i < 4; i++) {
        int r0 = bm + wm * 64 + i * 16;
        #pragma unroll
        for (int j = 0; j < 2; j++) {
            int c0 = bn + wn * 32 + j * 16;
            if (c0 < N)
                wmma::store_matrix_sync(&C[(size_t)r0 * N + c0], acc[i][j], N, wmma::mem_row_major);
        }
    }
}

// ---------------- conv1d (K=4, causal, per-batch padding) + SiLU -------------
__global__ void conv_silu_kernel(const float* __restrict__ cw, const float* __restrict__ cb)
{
    int c = blockIdx.x * 256 + threadIdx.x;
    int t = blockIdx.y;
    if (c >= CONVD) return;
    int pos = t & (LSEQ - 1);
    const float* col = g_zx + INTERN + c;
    float w0 = cw[c*4+0], w1 = cw[c*4+1], w2 = cw[c*4+2], w3 = cw[c*4+3];
    float v = cb[c];
    float x3 = col[(size_t)t * PROJN];
    float x2 = (pos >= 1) ? col[(size_t)(t-1) * PROJN] : 0.f;
    float x1 = (pos >= 2) ? col[(size_t)(t-2) * PROJN] : 0.f;
    float x0 = (pos >= 3) ? col[(size_t)(t-3) * PROJN] : 0.f;
    v += w0*x0 + w1*x1 + w2*x2 + w3*x3;
    g_xbc[(size_t)t * CONVD + c] = v / (1.f + expf(-v));
}

// ---------------- dt: softplus + dA cumsum per chunk -------------------------
__global__ void dt_kernel(const float* __restrict__ dtb, const float* __restrict__ alog)
{
    int bc = blockIdx.x;       // 0..15
    int h = threadIdx.x;       // 0..63
    int t0 = bc * CHUNK;
    float bias = dtb[h];
    float A = -expf(alog[h]);
    float cs = 0.f;
    for (int j = 0; j < CHUNK; j++) {
        int t = t0 + j;
        float raw = g_zx[(size_t)t * PROJN + INTERN + CONVD + h] + bias;
        float dtv = (raw > 20.f) ? raw : log1pf(expf(raw));
        g_dtsp[t * NHEAD + h] = dtv;
        cs += dtv * A;
        g_dacs[t * NHEAD + h] = cs;
    }
}

// ---------------- per-chunk states: S[p,n] = sum_j x[j,p] w[j] B[j,n] --------
__global__ __launch_bounds__(256) void states_kernel()
{
    int h = blockIdx.x, bc = blockIdx.y;
    int g = h >> 3;
    int t0 = bc * CHUNK;
    int tlast = t0 + CHUNK - 1;
    __shared__ float xw[32][64];
    __shared__ float Bs[32][128];
    __shared__ float ws[32];
    int tid = threadIdx.x;
    int tp = tid & 15;     // p block of 4
    int tn = tid >> 4;     // n block of 8
    float acc[4][8];
    #pragma unroll
    for (int i = 0; i < 4; i++)
        #pragma unroll
        for (int k = 0; k < 8; k++) acc[i][k] = 0.f;
    float daL = g_dacs[tlast * NHEAD + h];

    for (int j0 = 0; j0 < CHUNK; j0 += 32) {
        if (tid < 32) {
            int t = t0 + j0 + tid;
            ws[tid] = expf(daL - g_dacs[t * NHEAD + h]) * g_dtsp[t * NHEAD + h];
        }
        __syncthreads();
        for (int e = tid; e < 32*64; e += 256) {
            int j = e >> 6, p = e & 63;
            int t = t0 + j0 + j;
            xw[j][p] = g_xbc[(size_t)t * CONVD + h * HEADP + p] * ws[j];
        }
        for (int e = tid; e < 32*128; e += 256) {
            int j = e >> 7, n = e & 127;
            int t = t0 + j0 + j;
            Bs[j][n] = g_xbc[(size_t)t * CONVD + INTERN + g * NSTATE + n];
        }
        __syncthreads();
        #pragma unroll 4
        for (int j = 0; j < 32; j++) {
            float4 xv = *(const float4*)&xw[j][tp*4];
            float4 b0 = *(const float4*)&Bs[j][tn*8];
            float4 b1 = *(const float4*)&Bs[j][tn*8+4];
            float xr[4] = {xv.x, xv.y, xv.z, xv.w};
            float br[8] = {b0.x,b0.y,b0.z,b0.w,b1.x,b1.y,b1.z,b1.w};
            #pragma unroll
            for (int i = 0; i < 4; i++)
                #pragma unroll
                for (int k = 0; k < 8; k++)
                    acc[i][k] += xr[i] * br[k];
        }
        __syncthreads();
    }
    float* S = g_states + ((size_t)bc * NHEAD + h) * HEADP * NSTATE;
    #pragma unroll
    for (int i = 0; i < 4; i++)
        #pragma unroll
        for (int k = 0; k < 8; k++)
            S[(tp*4 + i) * NSTATE + tn*8 + k] = acc[i][k];
}

// ---------------- inter-chunk scan ------------------------------------------
__global__ void scan_kernel()
{
    int b = blockIdx.x >> 6;
    int h = blockIdx.x & 63;
    for (int e = threadIdx.x; e < HEADP * NSTATE; e += 256) {
        float run = 0.f;
        for (int z = 0; z < NCHUNK; z++) {
            int bc = b * NCHUNK + z;
            size_t off = ((size_t)bc * NHEAD + h) * HEADP * NSTATE + e;
            g_prev[off] = run;
            int tlast = bc * CHUNK + CHUNK - 1;
            float dec = expf(g_dacs[tlast * NHEAD + h]);
            run = dec * run + g_states[off];
        }
    }
}

// ---------------- fused Y_diag + Y_off + D*x ---------------------------------
// block = (itile, h, bc); computes 64 tokens x 64 headdim
__global__ __launch_bounds__(256) void ymain_kernel(const float* __restrict__ Dp)
{
    int it = blockIdx.x, h = blockIdx.y, bc = blockIdx.z;
    int g = h >> 3;
    int t0 = bc * CHUNK;
    int i0 = it * 64;
    extern __shared__ float sm[];
    float* Cs  = sm;             // [64][129]
    float* Js  = Cs + 64*129;    // [64][129]  (prev or B_j)
    float* Xs  = Js + 64*129;    // [64][65]
    float* Ss  = Xs + 64*65;     // [64][65]
    float* dai = Ss + 64*65;     // [64]
    float* eiv = dai + 64;       // [64]
    float* daj = eiv + 64;       // [64]
    float* dtj = daj + 64;       // [64]

    int tid = threadIdx.x;
    int tx = tid & 15, ty = tid >> 4;

    // load C_i tile and dA_cs for i-rows
    for (int e = tid; e < 64*128; e += 256) {
        int i = e >> 7, n = e & 127;
        Cs[i*129 + n] = g_xbc[(size_t)(t0 + i0 + i) * CONVD + INTERN + NGRP*NSTATE + g*NSTATE + n];
    }
    if (tid < 64) {
        float d = g_dacs[(t0 + i0 + tid) * NHEAD + h];
        dai[tid] = d;
        eiv[tid] = expf(d);
    }
    // load prev state [p][n]
    const float* prev = g_prev + ((size_t)bc * NHEAD + h) * HEADP * NSTATE;
    for (int e = tid; e < 64*128; e += 256) {
        int p = e >> 7, n = e & 127;
        Js[p*129 + n] = prev[p * NSTATE + n];
    }
    __syncthreads();

    // Y_off: acc[i][p] = ei[i] * sum_n C[i,n]*prev[p,n]
    float acc[4][4];
    {
        float off[4][4];
        #pragma unroll
        for (int i = 0; i < 4; i++)
            #pragma unroll
            for (int p = 0; p < 4; p++) off[i][p] = 0.f;
        #pragma unroll 4
        for (int n = 0; n < 128; n++) {
            float a[4], bv[4];
            #pragma unroll
            for (int i = 0; i < 4; i++) a[i] = Cs[(ty*4 + i)*129 + n];
            #pragma unroll
            for (int p = 0; p < 4; p++) bv[p] = Js[(tx*4 + p)*129 + n];
            #pragma unroll
            for (int i = 0; i < 4; i++)
                #pragma unroll
                for (int p = 0; p < 4; p++) off[i][p] += a[i] * bv[p];
        }
        #pragma unroll
        for (int i = 0; i < 4; i++)
            #pragma unroll
            for (int p = 0; p < 4; p++) acc[i][p] = off[i][p] * eiv[ty*4 + i];
    }
    __syncthreads();

    // Y_diag: loop over j-tiles <= i-tile
    for (int jt = 0; jt <= it; jt++) {
        int j0 = jt * 64;
        for (int e = tid; e < 64*128; e += 256) {
            int j = e >> 7, n = e & 127;
            Js[j*129 + n] = g_xbc[(size_t)(t0 + j0 + j) * CONVD + INTERN + g*NSTATE + n];
        }
        for (int e = tid; e < 64*64; e += 256) {
            int j = e >> 6, p = e & 63;
            Xs[j*65 + p] = g_xbc[(size_t)(t0 + j0 + j) * CONVD + h * HEADP + p];
        }
        if (tid < 64) {
            int t = t0 + j0 + tid;
            daj[tid] = g_dacs[t * NHEAD + h];
            dtj[tid] = g_dtsp[t * NHEAD + h];
        }
        __syncthreads();

        // S = C_i . B_j^T over N=128
        float s[4][4];
        #pragma unroll
        for (int i = 0; i < 4; i++)
            #pragma unroll
            for (int j = 0; j < 4; j++) s[i][j] = 0.f;
        #pragma unroll 4
        for (int n = 0; n < 128; n++) {
            float a[4], bv[4];
            #pragma unroll
            for (int i = 0; i < 4; i++) a[i] = Cs[(ty*4 + i)*129 + n];
            #pragma unroll
            for (int j = 0; j < 4; j++) bv[j] = Js[(tx*4 + j)*129 + n];
            #pragma unroll
            for (int i = 0; i < 4; i++)
                #pragma unroll
                for (int j = 0; j < 4; j++) s[i][j] += a[i] * bv[j];
        }
        // mask + decay + dt, stage to smem
        #pragma unroll
        for (int ii = 0; ii < 4; ii++) {
            int il = ty*4 + ii;
            int ig = i0 + il;
            #pragma unroll
            for (int jj = 0; jj < 4; jj++) {
                int jl = tx*4 + jj;
                int jg = j0 + jl;
                float v = 0.f;
                if (ig >= jg) v = s[ii][jj] * expf(dai[il] - daj[jl]) * dtj[jl];
                Ss[il*65 + jl] = v;
            }
        }
        __syncthreads();
        // acc += S @ x_j
        #pragma unroll 4
        for (int j = 0; j < 64; j++) {
            float a[4], bv[4];
            #pragma unroll
            for (int i = 0; i < 4; i++) a[i] = Ss[(ty*4 + i)*65 + j];
            #pragma unroll
            for (int p = 0; p < 4; p++) bv[p] = Xs[j*65 + tx*4 + p];
            #pragma unroll
            for (int i = 0; i < 4; i++)
                #pragma unroll
                for (int p = 0; p < 4; p++) acc[i][p] += a[i] * bv[p];
        }
        __syncthreads();
    }

    // epilogue: + D[h] * x_i ; write y
    float Dh = Dp[h];
    #pragma unroll
    for (int ii = 0; ii < 4; ii++) {
        int t = t0 + i0 + ty*4 + ii;
        #pragma unroll
        for (int pp = 0; pp < 4; pp++) {
            int p = tx*4 + pp;
            float xv = g_xbc[(size_t)t * CONVD + h * HEADP + p];
            g_y[(size_t)t * INTERN + h * HEADP + p] = acc[ii][pp] + Dh * xv;
        }
    }
}

// ---------------- RMS norm + silu(z) gate (in-place, tf32-rounded output) ----
__global__ void normgate_kernel(const float* __restrict__ nw)
{
    int t = blockIdx.x;
    float s = 0.f;
    for (int c = threadIdx.x; c < INTERN; c += 256) {
        float v = g_y[(size_t)t * INTERN + c];
        s += v * v;
    }
    __shared__ float red[8];
    #pragma unroll
    for (int o = 16; o; o >>= 1) s += __shfl_xor_sync(0xffffffffu, s, o);
    if ((threadIdx.x & 31) == 0) red[threadIdx.x >> 5] = s;
    __syncthreads();
    if (threadIdx.x < 8) {
        float v = red[threadIdx.x];
        #pragma unroll
        for (int o = 4; o; o >>= 1) v += __shfl_xor_sync(0xffu, v, o);
        if (threadIdx.x == 0) red[0] = v;
    }
    __syncthreads();
    float inv = rsqrtf(red[0] / (float)INTERN + EPSV);
    for (int c = threadIdx.x; c < INTERN; c += 256) {
        float v = g_y[(size_t)t * INTERN + c] * inv * nw[c];
        float z = g_zx[(size_t)t * PROJN + c];
        // pre-round for GEMM2 (same value the stage-time cvt would produce)
        g_y[(size_t)t * INTERN + c] = to_tf32_rn(v * (z / (1.f + expf(-z))));
    }
}

// ---------------- launch ------------------------------------------------------
extern "C" void kernel_launch(void* const* d_in, const int* in_sizes, int n_in,
                              void* d_out, int out_size)
{
    const float* hs    = (const float*)d_in[0];
    const float* w_in  = (const float*)d_in[1];
    const float* cw    = (const float*)d_in[2];
    const float* cb    = (const float*)d_in[3];
    const float* dtb   = (const float*)d_in[4];
    const float* alog  = (const float*)d_in[5];
    const float* Dp    = (const float*)d_in[6];
    const float* nw    = (const float*)d_in[7];
    const float* w_out = (const float*)d_in[8];
    float* out = (float*)d_out;

    float *zx, *y, *ar, *br, *cr;
    cudaGetSymbolAddress((void**)&zx, g_zx);
    cudaGetSymbolAddress((void**)&y, g_y);
    cudaGetSymbolAddress((void**)&ar, g_ar);
    cudaGetSymbolAddress((void**)&br, g_br);
    cudaGetSymbolAddress((void**)&cr, g_cr);

    cudaFuncSetAttribute(gemm_tf32, cudaFuncAttributeMaxDynamicSharedMemorySize, GSMEM);

    size_t ysmem = (size_t)(64*129*2 + 64*65*2 + 4*64) * sizeof(float);
    cudaFuncSetAttribute(ymain_kernel, cudaFuncAttributeMaxDynamicSharedMemorySize, (int)ysmem);

    // 0) pre-round GEMM operands to tf32 (bitwise same as stage-time rounding)
    round_tf32_kernel<<<2048, 256>>>(hs,    ar, (BT * HIDN) / 4);
    round_tf32_kernel<<<2048, 256>>>(w_in,  br, (PROJN * HIDN) / 4);
    round_tf32_kernel<<<2048, 256>>>(w_out, cr, (HIDN * INTERN) / 4);

    // 1) in_proj GEMM: [4096,10304] = [4096,2048] x [10304,2048]^T  (tf32 TC)
    gemm_tf32<<<dim3((PROJN + 127) / 128, BT / 128), 256, GSMEM>>>(ar, br, zx, BT, PROJN, HIDN);
    // 2) conv + silu
    conv_silu_kernel<<<dim3(CONVD / 256, BT), 256>>>(cw, cb);
    // 3) dt softplus + dA cumsum
    dt_kernel<<<NBC, NHEAD>>>(dtb, alog);
    // 4) per-chunk states
    states_kernel<<<dim3(NHEAD, NBC), 256>>>();
    // 5) inter-chunk scan
    scan_kernel<<<NBATCH * NHEAD, 256>>>();
    // 6) fused diag + off + D*x
    ymain_kernel<<<dim3(CHUNK / 64, NHEAD, NBC), 256, ysmem>>>(Dp);
    // 7) rmsnorm + gate (writes tf32-rounded y)
    normgate_kernel<<<BT, 256>>>(nw);
    // 8) out_proj GEMM: [4096,2048] = [4096,4096] x [2048,4096]^T  (tf32 TC)
    gemm_tf32<<<dim3(HIDN / 128, BT / 128), 256, GSMEM>>>(y, cr, out, BT, HIDN, INTERN);
}

// round 16
// speedup vs baseline: 1.2060x; 1.0531x over previous
#include <cuda_runtime.h>
#include <mma.h>
#include <math.h>
#include <cstdint>
#include <stdint.h>

using namespace nvcuda;

#define HIDN   2048
#define INTERN 4096
#define CONVD  6144
#define PROJN  10304
#define NHEAD  64
#define HEADP  64
#define NGRP   8
#define NSTATE 128
#define CHUNK  256
#define LSEQ   2048
#define NBATCH 2
#define NCHUNK 8
#define BT     4096          // total tokens
#define NBC    16            // NBATCH*NCHUNK
#define EPSV   1e-5f

// ---------------- scratch (device globals; no allocation) ----------------
__device__ float g_zx[(size_t)BT * PROJN];        // in_proj output
__device__ float g_xbc[(size_t)BT * CONVD];       // conv+silu output
__device__ float g_dtsp[BT * NHEAD];              // softplus(dt)
__device__ float g_dacs[BT * NHEAD];              // cumsum(dt*A) per chunk
__device__ float g_states[(size_t)NBC * NHEAD * HEADP * NSTATE];
__device__ float g_prev[(size_t)NBC * NHEAD * HEADP * NSTATE];
__device__ float g_y[(size_t)BT * INTERN];
// pre-rounded (tf32) GEMM operands
__device__ float g_ar[(size_t)BT * HIDN];         // hs rounded
__device__ float g_br[(size_t)PROJN * HIDN];      // in_proj_w rounded
__device__ float g_cr[(size_t)HIDN * INTERN];     // out_proj_w rounded

__device__ __forceinline__ float to_tf32_rn(float x) {
    float r;
    asm("cvt.rna.tf32.f32 %0, %1;" : "=f"(r) : "f"(x));
    return r;
}

__device__ __forceinline__ void cp_async16(unsigned int saddr, const void* gptr, bool pred) {
    int sz = pred ? 16 : 0;
    asm volatile("cp.async.cg.shared.global [%0], [%1], 16, %2;"
                 :: "r"(saddr), "l"(gptr), "r"(sz) : "memory");
}
__device__ __forceinline__ void cp_commit() {
    asm volatile("cp.async.commit_group;" ::: "memory");
}
template <int N>
__device__ __forceinline__ void cp_wait() {
    asm volatile("cp.async.wait_group %0;" :: "n"(N) : "memory");
}

// ---------------- pre-round: out[i] = tf32_rn(in[i]), float4 grid-stride ----
__global__ void round_tf32_kernel(const float* __restrict__ in, float* __restrict__ out, int n4)
{
    int i = blockIdx.x * blockDim.x + threadIdx.x;
    int stride = gridDim.x * blockDim.x;
    for (; i < n4; i += stride) {
        float4 v = ((const float4*)in)[i];
        v.x = to_tf32_rn(v.x); v.y = to_tf32_rn(v.y);
        v.z = to_tf32_rn(v.z); v.w = to_tf32_rn(v.w);
        ((float4*)out)[i] = v;
    }
}

// ---------------- TF32 tensor-core GEMM: C[M,N] = A[M,K] * B[N,K]^T ----------
// Pre-rounded inputs. Block tile 128(M) x 256(N), warp tile 64x64 (4x4 frags),
// BK=32, 256 threads = 8 warps (2x4). cp.async double buffer.
#define LDA 40
#define A_F (128 * LDA)              // A floats per stage
#define B_F (256 * LDA)              // B floats per stage
#define STG_F (A_F + B_F)            // floats per stage
#define GSMEM (2 * STG_F * 4)        // bytes, ~123 KB

__global__ __launch_bounds__(256, 1) void gemm_tf32(
    const float* __restrict__ A, const float* __restrict__ B,
    float* __restrict__ C, int M, int N, int K)
{
    extern __shared__ float sm[];    // [2][A | B]

    int bm = blockIdx.y * 128;
    int bn = blockIdx.x * 256;
    int tid = threadIdx.x;
    int wid = tid >> 5;
    int wm = wid >> 2;          // 0..1  (64-row strip)
    int wn = wid & 3;           // 0..3  (64-col strip)

    // A staging: thread -> row tid>>1, half-row (tid&1)*16, 4 x float4
    int arow = tid >> 1;
    int akc  = (tid & 1) * 16;
    const float* Ag = A + (size_t)(bm + arow) * K + akc;
    // B staging: thread -> full row tid (32 floats = 8 x float4)
    int brow = bn + tid;
    bool bvalid = brow < N;
    const float* Bg = B + (size_t)(bvalid ? brow : 0) * K;

    unsigned int smem_u32 = (unsigned int)__cvta_generic_to_shared(sm);
    unsigned int a_off = (unsigned int)((arow * LDA + akc) * 4);
    unsigned int b_off = (unsigned int)((A_F + tid * LDA) * 4);

    int nk = K >> 5;

    auto issue = [&](int t) {
        int buf = t & 1;
        unsigned int sb = smem_u32 + (unsigned int)(buf * STG_F * 4);
        int koff = t * 32;
        unsigned int da = sb + a_off;
        #pragma unroll
        for (int v = 0; v < 4; v++)
            cp_async16(da + v * 16, Ag + koff + v * 4, true);
        unsigned int db = sb + b_off;
        #pragma unroll
        for (int v = 0; v < 8; v++)
            cp_async16(db + v * 16, Bg + koff + v * 4, bvalid);
    };

    wmma::fragment<wmma::accumulator, 16, 16, 8, float> acc[4][4];
    #pragma unroll
    for (int i = 0; i < 4; i++)
        #pragma unroll
        for (int j = 0; j < 4; j++)
            wmma::fill_fragment(acc[i][j], 0.0f);

    issue(0); cp_commit();

    for (int t = 0; t < nk; t++) {
        cp_wait<0>();
        __syncthreads();                 // stage t visible; prior compute done

        if (t + 1 < nk) { issue(t + 1); cp_commit(); }   // overlap with compute

        const float* Ab = sm + (size_t)(t & 1) * STG_F;
        const float* Bb = Ab + A_F;

        #pragma unroll
        for (int ks = 0; ks < 4; ks++) {
            wmma::fragment<wmma::matrix_a, 16, 16, 8, wmma::precision::tf32, wmma::row_major> af[4];
            wmma::fragment<wmma::matrix_b, 16, 16, 8, wmma::precision::tf32, wmma::col_major> bf[4];
            #pragma unroll
            for (int i = 0; i < 4; i++)
                wmma::load_matrix_sync(af[i], &Ab[(wm * 64 + i * 16) * LDA + ks * 8], LDA);
            #pragma unroll
            for (int j = 0; j < 4; j++)
                wmma::load_matrix_sync(bf[j], &Bb[(wn * 64 + j * 16) * LDA + ks * 8], LDA);
            #pragma unroll
            for (int i = 0; i < 4; i++)
                #pragma unroll
                for (int j = 0; j < 4; j++)
                    wmma::mma_sync(acc[i][j], af[i], bf[j], acc[i][j]);
        }
    }

    // epilogue (N is a multiple of 16 here: 10304, 2048)
    #pragma unroll
    for (int i = 0; i < 4; i++) {
        int r0 = bm + wm * 64 + i * 16;
        #pragma unroll
        for (int j = 0; j < 4; j++) {
            int c0 = bn + wn * 64 + j * 16;
            if (c0 < N)
                wmma::store_matrix_sync(&C[(size_t)r0 * N + c0], acc[i][j], N, wmma::mem_row_major);
        }
    }
}

// ---------------- conv1d (K=4, causal, per-batch padding) + SiLU -------------
__global__ void conv_silu_kernel(const float* __restrict__ cw, const float* __restrict__ cb)
{
    int c = blockIdx.x * 256 + threadIdx.x;
    int t = blockIdx.y;
    if (c >= CONVD) return;
    int pos = t & (LSEQ - 1);
    const float* col = g_zx + INTERN + c;
    float w0 = cw[c*4+0], w1 = cw[c*4+1], w2 = cw[c*4+2], w3 = cw[c*4+3];
    float v = cb[c];
    float x3 = col[(size_t)t * PROJN];
    float x2 = (pos >= 1) ? col[(size_t)(t-1) * PROJN] : 0.f;
    float x1 = (pos >= 2) ? col[(size_t)(t-2) * PROJN] : 0.f;
    float x0 = (pos >= 3) ? col[(size_t)(t-3) * PROJN] : 0.f;
    v += w0*x0 + w1*x1 + w2*x2 + w3*x3;
    g_xbc[(size_t)t * CONVD + c] = v / (1.f + expf(-v));
}

// ---------------- dt: softplus + dA cumsum per chunk -------------------------
__global__ void dt_kernel(const float* __restrict__ dtb, const float* __restrict__ alog)
{
    int bc = blockIdx.x;       // 0..15
    int h = threadIdx.x;       // 0..63
    int t0 = bc * CHUNK;
    float bias = dtb[h];
    float A = -expf(alog[h]);
    float cs = 0.f;
    for (int j = 0; j < CHUNK; j++) {
        int t = t0 + j;
        float raw = g_zx[(size_t)t * PROJN + INTERN + CONVD + h] + bias;
        float dtv = (raw > 20.f) ? raw : log1pf(expf(raw));
        g_dtsp[t * NHEAD + h] = dtv;
        cs += dtv * A;
        g_dacs[t * NHEAD + h] = cs;
    }
}

// ---------------- per-chunk states: S[p,n] = sum_j x[j,p] w[j] B[j,n] --------
__global__ __launch_bounds__(256) void states_kernel()
{
    int h = blockIdx.x, bc = blockIdx.y;
    int g = h >> 3;
    int t0 = bc * CHUNK;
    int tlast = t0 + CHUNK - 1;
    __shared__ float xw[32][64];
    __shared__ float Bs[32][128];
    __shared__ float ws[32];
    int tid = threadIdx.x;
    int tp = tid & 15;     // p block of 4
    int tn = tid >> 4;     // n block of 8
    float acc[4][8];
    #pragma unroll
    for (int i = 0; i < 4; i++)
        #pragma unroll
        for (int k = 0; k < 8; k++) acc[i][k] = 0.f;
    float daL = g_dacs[tlast * NHEAD + h];

    for (int j0 = 0; j0 < CHUNK; j0 += 32) {
        if (tid < 32) {
            int t = t0 + j0 + tid;
            ws[tid] = expf(daL - g_dacs[t * NHEAD + h]) * g_dtsp[t * NHEAD + h];
        }
        __syncthreads();
        for (int e = tid; e < 32*64; e += 256) {
            int j = e >> 6, p = e & 63;
            int t = t0 + j0 + j;
            xw[j][p] = g_xbc[(size_t)t * CONVD + h * HEADP + p] * ws[j];
        }
        for (int e = tid; e < 32*128; e += 256) {
            int j = e >> 7, n = e & 127;
            int t = t0 + j0 + j;
            Bs[j][n] = g_xbc[(size_t)t * CONVD + INTERN + g * NSTATE + n];
        }
        __syncthreads();
        #pragma unroll 4
        for (int j = 0; j < 32; j++) {
            float4 xv = *(const float4*)&xw[j][tp*4];
            float4 b0 = *(const float4*)&Bs[j][tn*8];
            float4 b1 = *(const float4*)&Bs[j][tn*8+4];
            float xr[4] = {xv.x, xv.y, xv.z, xv.w};
            float br[8] = {b0.x,b0.y,b0.z,b0.w,b1.x,b1.y,b1.z,b1.w};
            #pragma unroll
            for (int i = 0; i < 4; i++)
                #pragma unroll
                for (int k = 0; k < 8; k++)
                    acc[i][k] += xr[i] * br[k];
        }
        __syncthreads();
    }
    float* S = g_states + ((size_t)bc * NHEAD + h) * HEADP * NSTATE;
    #pragma unroll
    for (int i = 0; i < 4; i++)
        #pragma unroll
        for (int k = 0; k < 8; k++)
            S[(tp*4 + i) * NSTATE + tn*8 + k] = acc[i][k];
}

// ---------------- inter-chunk scan ------------------------------------------
__global__ void scan_kernel()
{
    int b = blockIdx.x >> 6;
    int h = blockIdx.x & 63;
    for (int e = threadIdx.x; e < HEADP * NSTATE; e += 256) {
        float run = 0.f;
        for (int z = 0; z < NCHUNK; z++) {
            int bc = b * NCHUNK + z;
            size_t off = ((size_t)bc * NHEAD + h) * HEADP * NSTATE + e;
            g_prev[off] = run;
            int tlast = bc * CHUNK + CHUNK - 1;
            float dec = expf(g_dacs[tlast * NHEAD + h]);
            run = dec * run + g_states[off];
        }
    }
}

// ---------------- fused Y_diag + Y_off + D*x ---------------------------------
// block = (itile, h, bc); computes 64 tokens x 64 headdim
__global__ __launch_bounds__(256) void ymain_kernel(const float* __restrict__ Dp)
{
    int it = blockIdx.x, h = blockIdx.y, bc = blockIdx.z;
    int g = h >> 3;
    int t0 = bc * CHUNK;
    int i0 = it * 64;
    extern __shared__ float sm[];
    float* Cs  = sm;             // [64][129]
    float* Js  = Cs + 64*129;    // [64][129]  (prev or B_j)
    float* Xs  = Js + 64*129;    // [64][65]
    float* Ss  = Xs + 64*65;     // [64][65]
    float* dai = Ss + 64*65;     // [64]
    float* eiv = dai + 64;       // [64]
    float* daj = eiv + 64;       // [64]
    float* dtj = daj + 64;       // [64]

    int tid = threadIdx.x;
    int tx = tid & 15, ty = tid >> 4;

    // load C_i tile and dA_cs for i-rows
    for (int e = tid; e < 64*128; e += 256) {
        int i = e >> 7, n = e & 127;
        Cs[i*129 + n] = g_xbc[(size_t)(t0 + i0 + i) * CONVD + INTERN + NGRP*NSTATE + g*NSTATE + n];
    }
    if (tid < 64) {
        float d = g_dacs[(t0 + i0 + tid) * NHEAD + h];
        dai[tid] = d;
        eiv[tid] = expf(d);
    }
    // load prev state [p][n]
    const float* prev = g_prev + ((size_t)bc * NHEAD + h) * HEADP * NSTATE;
    for (int e = tid; e < 64*128; e += 256) {
        int p = e >> 7, n = e & 127;
        Js[p*129 + n] = prev[p * NSTATE + n];
    }
    __syncthreads();

    // Y_off: acc[i][p] = ei[i] * sum_n C[i,n]*prev[p,n]
    float acc[4][4];
    {
        float off[4][4];
        #pragma unroll
        for (int i = 0; i < 4; i++)
            #pragma unroll
            for (int p = 0; p < 4; p++) off[i][p] = 0.f;
        #pragma unroll 4
        for (int n = 0; n < 128; n++) {
            float a[4], bv[4];
            #pragma unroll
            for (int i = 0; i < 4; i++) a[i] = Cs[(ty*4 + i)*129 + n];
            #pragma unroll
            for (int p = 0; p < 4; p++) bv[p] = Js[(tx*4 + p)*129 + n];
            #pragma unroll
            for (int i = 0; i < 4; i++)
                #pragma unroll
                for (int p = 0; p < 4; p++) off[i][p] += a[i] * bv[p];
        }
        #pragma unroll
        for (int i = 0; i < 4; i++)
            #pragma unroll
            for (int p = 0; p < 4; p++) acc[i][p] = off[i][p] * eiv[ty*4 + i];
    }
    __syncthreads();

    // Y_diag: loop over j-tiles <= i-tile
    for (int jt = 0; jt <= it; jt++) {
        int j0 = jt * 64;
        for (int e = tid; e < 64*128; e += 256) {
            int j = e >> 7, n = e & 127;
            Js[j*129 + n] = g_xbc[(size_t)(t0 + j0 + j) * CONVD + INTERN + g*NSTATE + n];
        }
        for (int e = tid; e < 64*64; e += 256) {
            int j = e >> 6, p = e & 63;
            Xs[j*65 + p] = g_xbc[(size_t)(t0 + j0 + j) * CONVD + h * HEADP + p];
        }
        if (tid < 64) {
            int t = t0 + j0 + tid;
            daj[tid] = g_dacs[t * NHEAD + h];
            dtj[tid] = g_dtsp[t * NHEAD + h];
        }
        __syncthreads();

        // S = C_i . B_j^T over N=128
        float s[4][4];
        #pragma unroll
        for (int i = 0; i < 4; i++)
            #pragma unroll
            for (int j = 0; j < 4; j++) s[i][j] = 0.f;
        #pragma unroll 4
        for (int n = 0; n < 128; n++) {
            float a[4], bv[4];
            #pragma unroll
            for (int i = 0; i < 4; i++) a[i] = Cs[(ty*4 + i)*129 + n];
            #pragma unroll
            for (int j = 0; j < 4; j++) bv[j] = Js[(tx*4 + j)*129 + n];
            #pragma unroll
            for (int i = 0; i < 4; i++)
                #pragma unroll
                for (int j = 0; j < 4; j++) s[i][j] += a[i] * bv[j];
        }
        // mask + decay + dt, stage to smem
        #pragma unroll
        for (int ii = 0; ii < 4; ii++) {
            int il = ty*4 + ii;
            int ig = i0 + il;
            #pragma unroll
            for (int jj = 0; jj < 4; jj++) {
                int jl = tx*4 + jj;
                int jg = j0 + jl;
                float v = 0.f;
                if (ig >= jg) v = s[ii][jj] * expf(dai[il] - daj[jl]) * dtj[jl];
                Ss[il*65 + jl] = v;
            }
        }
        __syncthreads();
        // acc += S @ x_j
        #pragma unroll 4
        for (int j = 0; j < 64; j++) {
            float a[4], bv[4];
            #pragma unroll
            for (int i = 0; i < 4; i++) a[i] = Ss[(ty*4 + i)*65 + j];
            #pragma unroll
            for (int p = 0; p < 4; p++) bv[p] = Xs[j*65 + tx*4 + p];
            #pragma unroll
            for (int i = 0; i < 4; i++)
                #pragma unroll
                for (int p = 0; p < 4; p++) acc[i][p] += a[i] * bv[p];
        }
        __syncthreads();
    }

    // epilogue: + D[h] * x_i ; write y
    float Dh = Dp[h];
    #pragma unroll
    for (int ii = 0; ii < 4; ii++) {
        int t = t0 + i0 + ty*4 + ii;
        #pragma unroll
        for (int pp = 0; pp < 4; pp++) {
            int p = tx*4 + pp;
            float xv = g_xbc[(size_t)t * CONVD + h * HEADP + p];
            g_y[(size_t)t * INTERN + h * HEADP + p] = acc[ii][pp] + Dh * xv;
        }
    }
}

// ---------------- RMS norm + silu(z) gate (in-place, tf32-rounded output) ----
__global__ void normgate_kernel(const float* __restrict__ nw)
{
    int t = blockIdx.x;
    float s = 0.f;
    for (int c = threadIdx.x; c < INTERN; c += 256) {
        float v = g_y[(size_t)t * INTERN + c];
        s += v * v;
    }
    __shared__ float red[8];
    #pragma unroll
    for (int o = 16; o; o >>= 1) s += __shfl_xor_sync(0xffffffffu, s, o);
    if ((threadIdx.x & 31) == 0) red[threadIdx.x >> 5] = s;
    __syncthreads();
    if (threadIdx.x < 8) {
        float v = red[threadIdx.x];
        #pragma unroll
        for (int o = 4; o; o >>= 1) v += __shfl_xor_sync(0xffu, v, o);
        if (threadIdx.x == 0) red[0] = v;
    }
    __syncthreads();
    float inv = rsqrtf(red[0] / (float)INTERN + EPSV);
    for (int c = threadIdx.x; c < INTERN; c += 256) {
        float v = g_y[(size_t)t * INTERN + c] * inv * nw[c];
        float z = g_zx[(size_t)t * PROJN + c];
        // pre-round for GEMM2 (same value the stage-time cvt would produce)
        g_y[(size_t)t * INTERN + c] = to_tf32_rn(v * (z / (1.f + expf(-z))));
    }
}

// ---------------- launch ------------------------------------------------------
extern "C" void kernel_launch(void* const* d_in, const int* in_sizes, int n_in,
                              void* d_out, int out_size)
{
    const float* hs    = (const float*)d_in[0];
    const float* w_in  = (const float*)d_in[1];
    const float* cw    = (const float*)d_in[2];
    const float* cb    = (const float*)d_in[3];
    const float* dtb   = (const float*)d_in[4];
    const float* alog  = (const float*)d_in[5];
    const float* Dp    = (const float*)d_in[6];
    const float* nw    = (const float*)d_in[7];
    const float* w_out = (const float*)d_in[8];
    float* out = (float*)d_out;

    float *zx, *y, *ar, *br, *cr;
    cudaGetSymbolAddress((void**)&zx, g_zx);
    cudaGetSymbolAddress((void**)&y, g_y);
    cudaGetSymbolAddress((void**)&ar, g_ar);
    cudaGetSymbolAddress((void**)&br, g_br);
    cudaGetSymbolAddress((void**)&cr, g_cr);

    cudaFuncSetAttribute(gemm_tf32, cudaFuncAttributeMaxDynamicSharedMemorySize, GSMEM);

    size_t ysmem = (size_t)(64*129*2 + 64*65*2 + 4*64) * sizeof(float);
    cudaFuncSetAttribute(ymain_kernel, cudaFuncAttributeMaxDynamicSharedMemorySize, (int)ysmem);

    // 0) pre-round GEMM operands to tf32 (bitwise same as stage-time rounding)
    round_tf32_kernel<<<2048, 256>>>(hs,    ar, (BT * HIDN) / 4);
    round_tf32_kernel<<<2048, 256>>>(w_in,  br, (PROJN * HIDN) / 4);
    round_tf32_kernel<<<2048, 256>>>(w_out, cr, (HIDN * INTERN) / 4);

    // 1) in_proj GEMM: [4096,10304] = [4096,2048] x [10304,2048]^T  (tf32 TC)
    gemm_tf32<<<dim3((PROJN + 255) / 256, BT / 128), 256, GSMEM>>>(ar, br, zx, BT, PROJN, HIDN);
    // 2) conv + silu
    conv_silu_kernel<<<dim3(CONVD / 256, BT), 256>>>(cw, cb);
    // 3) dt softplus + dA cumsum
    dt_kernel<<<NBC, NHEAD>>>(dtb, alog);
    // 4) per-chunk states
    states_kernel<<<dim3(NHEAD, NBC), 256>>>();
    // 5) inter-chunk scan
    scan_kernel<<<NBATCH * NHEAD, 256>>>();
    // 6) fused diag + off + D*x
    ymain_kernel<<<dim3(CHUNK / 64, NHEAD, NBC), 256, ysmem>>>(Dp);
    // 7) rmsnorm + gate (writes tf32-rounded y)
    normgate_kernel<<<BT, 256>>>(nw);
    // 8) out_proj GEMM: [4096,2048] = [4096,4096] x [2048,4096]^T  (tf32 TC)
    gemm_tf32<<<dim3(HIDN / 256, BT / 128), 256, GSMEM>>>(y, cr, out, BT, HIDN, INTERN);
}

// round 17
// speedup vs baseline: 1.5125x; 1.2541x over previous
#include <cuda_runtime.h>
#include <math.h>
#include <cstdint>
#include <stdint.h>

#define HIDN   2048
#define INTERN 4096
#define CONVD  6144
#define PROJN  10304
#define NHEAD  64
#define HEADP  64
#define NGRP   8
#define NSTATE 128
#define CHUNK  256
#define LSEQ   2048
#define NBATCH 2
#define NCHUNK 8
#define BT     4096          // total tokens
#define NBC    16            // NBATCH*NCHUNK
#define EPSV   1e-5f

// ---------------- scratch (device globals; no allocation) ----------------
__device__ float g_zx[(size_t)BT * PROJN];        // in_proj output
__device__ float g_xbc[(size_t)BT * CONVD];       // conv+silu output
__device__ float g_dtsp[BT * NHEAD];              // softplus(dt)
__device__ float g_dacs[BT * NHEAD];              // cumsum(dt*A) per chunk
__device__ float g_states[(size_t)NBC * NHEAD * HEADP * NSTATE];
__device__ float g_prev[(size_t)NBC * NHEAD * HEADP * NSTATE];
__device__ float g_y[(size_t)BT * INTERN];        // ymain output (row-major)
__device__ float g_yr[(size_t)BT * INTERN];       // normgate output, TILED for GEMM2
// pre-rounded + fragment-major-tiled GEMM operands
__device__ float g_ar[(size_t)BT * HIDN];         // hs    (A-type tiles)
__device__ float g_br[(size_t)PROJN * HIDN];      // w_in  (B-type tiles)
__device__ float g_cr[(size_t)HIDN * INTERN];     // w_out (B-type tiles)

__device__ __forceinline__ float to_tf32_rn(float x) {
    float r;
    asm("cvt.rna.tf32.f32 %0, %1;" : "=f"(r) : "f"(x));
    return r;
}

__device__ __forceinline__ void cp_async16(unsigned int saddr, const void* gptr, bool pred) {
    int sz = pred ? 16 : 0;
    asm volatile("cp.async.cg.shared.global [%0], [%1], 16, %2;"
                 :: "r"(saddr), "l"(gptr), "r"(sz) : "memory");
}
__device__ __forceinline__ void cp_commit() {
    asm volatile("cp.async.commit_group;" ::: "memory");
}
template <int N>
__device__ __forceinline__ void cp_wait() {
    asm volatile("cp.async.wait_group %0;" :: "n"(N) : "memory");
}

// ---------------- permute+round: A-type (MxK row-major -> fragment tiles) ----
// A tile = 16x8, stored 128 floats: lane*4 + e; a0=(g,t) a1=(g+8,t) a2=(g,t+4) a3=(g+8,t+4)
__global__ void perm_a_kernel(const float* __restrict__ in, float* __restrict__ out,
                              int M, int K)
{
    size_t total = (size_t)M * K;
    int K8 = K >> 3;
    for (size_t o = (size_t)blockIdx.x * blockDim.x + threadIdx.x; o < total;
         o += (size_t)gridDim.x * blockDim.x) {
        size_t tile = o >> 7;
        int lane = ((int)(o >> 2)) & 31;
        int e = (int)(o & 3);
        int tm = (int)(tile / K8), tk = (int)(tile % K8);
        int g = lane >> 2, t = lane & 3;
        int r = tm * 16 + g + (e & 1) * 8;
        int c = tk * 8 + t + (e >> 1) * 4;
        out[o] = to_tf32_rn(in[(size_t)r * K + c]);
    }
}

// ---------------- permute+round: B-type (NxK row-major -> fragment tiles) ----
// B tile = 8(K)x8(N), stored 64 floats: lane*2 + e; b0=(k=t,n=g) b1=(k=t+4,n=g)
__global__ void perm_b_kernel(const float* __restrict__ in, float* __restrict__ out,
                              int N, int K)
{
    size_t total = (size_t)N * K;
    int K8 = K >> 3;
    for (size_t o = (size_t)blockIdx.x * blockDim.x + threadIdx.x; o < total;
         o += (size_t)gridDim.x * blockDim.x) {
        size_t tile = o >> 6;
        int lane = ((int)(o >> 1)) & 31;
        int e = (int)(o & 1);
        int tn = (int)(tile / K8), tk = (int)(tile % K8);
        int g = lane >> 2, t = lane & 3;
        int n = tn * 8 + g;
        int k = tk * 8 + t + e * 4;
        out[o] = to_tf32_rn(in[(size_t)n * K + k]);
    }
}

// ---------------- TF32 mma.sync GEMM: C[M,N] = A[M,K] * B[N,K]^T -------------
// A, B in fragment-major tiled layout. Block tile 128x256, warp tile 64x64,
// BK=32, 256 threads = 8 warps. cp.async double buffer; one LDS.128/LDS.64 per frag.
#define BM 128
#define BN 256
#define A_F 4096                 // floats per A stage (8 mtiles x 4 ktiles x 128)
#define B_F 8192                 // floats per B stage (32 ntiles x 4 ktiles x 64)
#define STG_F (A_F + B_F)
#define GSMEM (2 * STG_F * 4)    // 96 KB

__global__ __launch_bounds__(256) void gemm_tf32(
    const float* __restrict__ A, const float* __restrict__ B,
    float* __restrict__ C, int M, int N, int K)
{
    extern __shared__ float sm[];
    int K8 = K >> 3;
    int n8 = N >> 3;
    int tid = threadIdx.x, wid = tid >> 5, lane = tid & 31;
    int wm = wid >> 2, wn = wid & 3;
    int g = lane >> 2, tg = lane & 3;
    int bm = blockIdx.y * BM, bn = blockIdx.x * BN;
    int tm0 = bm >> 4, tn0 = bn >> 3;

    unsigned int smem_u = (unsigned int)__cvta_generic_to_shared(sm);

    auto issue = [&](int kb) {
        unsigned int sbase = smem_u + (unsigned int)((kb & 1) * STG_F * 4);
        int kb4 = kb * 4;
        // A stage: 1024 x 16B chunks; per m-tile-row: 4 contiguous k-tiles (2KB)
        #pragma unroll
        for (int v = 0; v < 4; v++) {
            int idx = v * 256 + tid;
            int tml = idx >> 7, rem = idx & 127;
            const float* src = A + ((size_t)(tm0 + tml) * K8 + kb4) * 128 + rem * 4;
            cp_async16(sbase + idx * 16, src, true);
        }
        // B stage: 2048 x 16B chunks; per n-tile: 4 contiguous k-tiles (1KB)
        #pragma unroll
        for (int v = 0; v < 8; v++) {
            int idx = v * 256 + tid;
            int tnl = idx >> 6, rem = idx & 63;
            bool valid = (tn0 + tnl) < n8;
            const float* src = valid
                ? B + ((size_t)(tn0 + tnl) * K8 + kb4) * 64 + rem * 4 : B;
            cp_async16(sbase + (unsigned int)(A_F * 4) + idx * 16, src, valid);
        }
    };

    float acc[4][8][4];
    #pragma unroll
    for (int i = 0; i < 4; i++)
        #pragma unroll
        for (int j = 0; j < 8; j++)
            #pragma unroll
            for (int e = 0; e < 4; e++) acc[i][j][e] = 0.f;

    int nk = K >> 5;
    issue(0); cp_commit();

    for (int t = 0; t < nk; t++) {
        cp_wait<0>();
        __syncthreads();
        if (t + 1 < nk) { issue(t + 1); cp_commit(); }

        const float* Ab = sm + (size_t)(t & 1) * STG_F;
        const float* Bb = Ab + A_F;

        #pragma unroll
        for (int kt = 0; kt < 4; kt++) {
            uint4 af[4]; uint2 bf[8];
            #pragma unroll
            for (int i = 0; i < 4; i++)
                af[i] = *(const uint4*)(Ab + ((wm * 4 + i) * 4 + kt) * 128 + lane * 4);
            #pragma unroll
            for (int j = 0; j < 8; j++)
                bf[j] = *(const uint2*)(Bb + ((wn * 8 + j) * 4 + kt) * 64 + lane * 2);
            #pragma unroll
            for (int i = 0; i < 4; i++)
                #pragma unroll
                for (int j = 0; j < 8; j++)
                    asm volatile(
                        "mma.sync.aligned.m16n8k8.row.col.f32.tf32.tf32.f32 "
                        "{%0,%1,%2,%3}, {%4,%5,%6,%7}, {%8,%9}, {%0,%1,%2,%3};"
                        : "+f"(acc[i][j][0]), "+f"(acc[i][j][1]),
                          "+f"(acc[i][j][2]), "+f"(acc[i][j][3])
                        : "r"(af[i].x), "r"(af[i].y), "r"(af[i].z), "r"(af[i].w),
                          "r"(bf[j].x), "r"(bf[j].y));
        }
    }

    // epilogue: c0=(g,2t) c1=(g,2t+1) c2=(g+8,2t) c3=(g+8,2t+1)
    #pragma unroll
    for (int i = 0; i < 4; i++) {
        int r0 = bm + wm * 64 + i * 16 + g;
        #pragma unroll
        for (int j = 0; j < 8; j++) {
            int c0 = bn + wn * 64 + j * 8 + tg * 2;
            if (c0 < N) {
                *(float2*)&C[(size_t)r0 * N + c0]       = make_float2(acc[i][j][0], acc[i][j][1]);
                *(float2*)&C[(size_t)(r0 + 8) * N + c0] = make_float2(acc[i][j][2], acc[i][j][3]);
            }
        }
    }
}

// ---------------- conv1d (K=4, causal, per-batch padding) + SiLU -------------
__global__ void conv_silu_kernel(const float* __restrict__ cw, const float* __restrict__ cb)
{
    int c = blockIdx.x * 256 + threadIdx.x;
    int t = blockIdx.y;
    if (c >= CONVD) return;
    int pos = t & (LSEQ - 1);
    const float* col = g_zx + INTERN + c;
    float w0 = cw[c*4+0], w1 = cw[c*4+1], w2 = cw[c*4+2], w3 = cw[c*4+3];
    float v = cb[c];
    float x3 = col[(size_t)t * PROJN];
    float x2 = (pos >= 1) ? col[(size_t)(t-1) * PROJN] : 0.f;
    float x1 = (pos >= 2) ? col[(size_t)(t-2) * PROJN] : 0.f;
    float x0 = (pos >= 3) ? col[(size_t)(t-3) * PROJN] : 0.f;
    v += w0*x0 + w1*x1 + w2*x2 + w3*x3;
    g_xbc[(size_t)t * CONVD + c] = v / (1.f + expf(-v));
}

// ---------------- dt: softplus + dA cumsum per chunk -------------------------
__global__ void dt_kernel(const float* __restrict__ dtb, const float* __restrict__ alog)
{
    int bc = blockIdx.x;       // 0..15
    int h = threadIdx.x;       // 0..63
    int t0 = bc * CHUNK;
    float bias = dtb[h];
    float A = -expf(alog[h]);
    float cs = 0.f;
    for (int j = 0; j < CHUNK; j++) {
        int t = t0 + j;
        float raw = g_zx[(size_t)t * PROJN + INTERN + CONVD + h] + bias;
        float dtv = (raw > 20.f) ? raw : log1pf(expf(raw));
        g_dtsp[t * NHEAD + h] = dtv;
        cs += dtv * A;
        g_dacs[t * NHEAD + h] = cs;
    }
}

// ---------------- per-chunk states: S[p,n] = sum_j x[j,p] w[j] B[j,n] --------
__global__ __launch_bounds__(256) void states_kernel()
{
    int h = blockIdx.x, bc = blockIdx.y;
    int g = h >> 3;
    int t0 = bc * CHUNK;
    int tlast = t0 + CHUNK - 1;
    __shared__ float xw[32][64];
    __shared__ float Bs[32][128];
    __shared__ float ws[32];
    int tid = threadIdx.x;
    int tp = tid & 15;     // p block of 4
    int tn = tid >> 4;     // n block of 8
    float acc[4][8];
    #pragma unroll
    for (int i = 0; i < 4; i++)
        #pragma unroll
        for (int k = 0; k < 8; k++) acc[i][k] = 0.f;
    float daL = g_dacs[tlast * NHEAD + h];

    for (int j0 = 0; j0 < CHUNK; j0 += 32) {
        if (tid < 32) {
            int t = t0 + j0 + tid;
            ws[tid] = expf(daL - g_dacs[t * NHEAD + h]) * g_dtsp[t * NHEAD + h];
        }
        __syncthreads();
        for (int e = tid; e < 32*64; e += 256) {
            int j = e >> 6, p = e & 63;
            int t = t0 + j0 + j;
            xw[j][p] = g_xbc[(size_t)t * CONVD + h * HEADP + p] * ws[j];
        }
        for (int e = tid; e < 32*128; e += 256) {
            int j = e >> 7, n = e & 127;
            int t = t0 + j0 + j;
            Bs[j][n] = g_xbc[(size_t)t * CONVD + INTERN + g * NSTATE + n];
        }
        __syncthreads();
        #pragma unroll 4
        for (int j = 0; j < 32; j++) {
            float4 xv = *(const float4*)&xw[j][tp*4];
            float4 b0 = *(const float4*)&Bs[j][tn*8];
            float4 b1 = *(const float4*)&Bs[j][tn*8+4];
            float xr[4] = {xv.x, xv.y, xv.z, xv.w};
            float br[8] = {b0.x,b0.y,b0.z,b0.w,b1.x,b1.y,b1.z,b1.w};
            #pragma unroll
            for (int i = 0; i < 4; i++)
                #pragma unroll
                for (int k = 0; k < 8; k++)
                    acc[i][k] += xr[i] * br[k];
        }
        __syncthreads();
    }
    float* S = g_states + ((size_t)bc * NHEAD + h) * HEADP * NSTATE;
    #pragma unroll
    for (int i = 0; i < 4; i++)
        #pragma unroll
        for (int k = 0; k < 8; k++)
            S[(tp*4 + i) * NSTATE + tn*8 + k] = acc[i][k];
}

// ---------------- inter-chunk scan ------------------------------------------
__global__ void scan_kernel()
{
    int b = blockIdx.x >> 6;
    int h = blockIdx.x & 63;
    for (int e = threadIdx.x; e < HEADP * NSTATE; e += 256) {
        float run = 0.f;
        for (int z = 0; z < NCHUNK; z++) {
            int bc = b * NCHUNK + z;
            size_t off = ((size_t)bc * NHEAD + h) * HEADP * NSTATE + e;
            g_prev[off] = run;
            int tlast = bc * CHUNK + CHUNK - 1;
            float dec = expf(g_dacs[tlast * NHEAD + h]);
            run = dec * run + g_states[off];
        }
    }
}

// ---------------- fused Y_diag + Y_off + D*x ---------------------------------
// block = (itile, h, bc); computes 64 tokens x 64 headdim
__global__ __launch_bounds__(256) void ymain_kernel(const float* __restrict__ Dp)
{
    int it = blockIdx.x, h = blockIdx.y, bc = blockIdx.z;
    int g = h >> 3;
    int t0 = bc * CHUNK;
    int i0 = it * 64;
    extern __shared__ float sm[];
    float* Cs  = sm;             // [64][129]
    float* Js  = Cs + 64*129;    // [64][129]  (prev or B_j)
    float* Xs  = Js + 64*129;    // [64][65]
    float* Ss  = Xs + 64*65;     // [64][65]
    float* dai = Ss + 64*65;     // [64]
    float* eiv = dai + 64;       // [64]
    float* daj = eiv + 64;       // [64]
    float* dtj = daj + 64;       // [64]

    int tid = threadIdx.x;
    int tx = tid & 15, ty = tid >> 4;

    // load C_i tile and dA_cs for i-rows
    for (int e = tid; e < 64*128; e += 256) {
        int i = e >> 7, n = e & 127;
        Cs[i*129 + n] = g_xbc[(size_t)(t0 + i0 + i) * CONVD + INTERN + NGRP*NSTATE + g*NSTATE + n];
    }
    if (tid < 64) {
        float d = g_dacs[(t0 + i0 + tid) * NHEAD + h];
        dai[tid] = d;
        eiv[tid] = expf(d);
    }
    // load prev state [p][n]
    const float* prev = g_prev + ((size_t)bc * NHEAD + h) * HEADP * NSTATE;
    for (int e = tid; e < 64*128; e += 256) {
        int p = e >> 7, n = e & 127;
        Js[p*129 + n] = prev[p * NSTATE + n];
    }
    __syncthreads();

    // Y_off: acc[i][p] = ei[i] * sum_n C[i,n]*prev[p,n]
    float acc[4][4];
    {
        float off[4][4];
        #pragma unroll
        for (int i = 0; i < 4; i++)
            #pragma unroll
            for (int p = 0; p < 4; p++) off[i][p] = 0.f;
        #pragma unroll 4
        for (int n = 0; n < 128; n++) {
            float a[4], bv[4];
            #pragma unroll
            for (int i = 0; i < 4; i++) a[i] = Cs[(ty*4 + i)*129 + n];
            #pragma unroll
            for (int p = 0; p < 4; p++) bv[p] = Js[(tx*4 + p)*129 + n];
            #pragma unroll
            for (int i = 0; i < 4; i++)
                #pragma unroll
                for (int p = 0; p < 4; p++) off[i][p] += a[i] * bv[p];
        }
        #pragma unroll
        for (int i = 0; i < 4; i++)
            #pragma unroll
            for (int p = 0; p < 4; p++) acc[i][p] = off[i][p] * eiv[ty*4 + i];
    }
    __syncthreads();

    // Y_diag: loop over j-tiles <= i-tile
    for (int jt = 0; jt <= it; jt++) {
        int j0 = jt * 64;
        for (int e = tid; e < 64*128; e += 256) {
            int j = e >> 7, n = e & 127;
            Js[j*129 + n] = g_xbc[(size_t)(t0 + j0 + j) * CONVD + INTERN + g*NSTATE + n];
        }
        for (int e = tid; e < 64*64; e += 256) {
            int j = e >> 6, p = e & 63;
            Xs[j*65 + p] = g_xbc[(size_t)(t0 + j0 + j) * CONVD + h * HEADP + p];
        }
        if (tid < 64) {
            int t = t0 + j0 + tid;
            daj[tid] = g_dacs[t * NHEAD + h];
            dtj[tid] = g_dtsp[t * NHEAD + h];
        }
        __syncthreads();

        // S = C_i . B_j^T over N=128
        float s[4][4];
        #pragma unroll
        for (int i = 0; i < 4; i++)
            #pragma unroll
            for (int j = 0; j < 4; j++) s[i][j] = 0.f;
        #pragma unroll 4
        for (int n = 0; n < 128; n++) {
            float a[4], bv[4];
            #pragma unroll
            for (int i = 0; i < 4; i++) a[i] = Cs[(ty*4 + i)*129 + n];
            #pragma unroll
            for (int j = 0; j < 4; j++) bv[j] = Js[(tx*4 + j)*129 + n];
            #pragma unroll
            for (int i = 0; i < 4; i++)
                #pragma unroll
                for (int j = 0; j < 4; j++) s[i][j] += a[i] * bv[j];
        }
        // mask + decay + dt, stage to smem
        #pragma unroll
        for (int ii = 0; ii < 4; ii++) {
            int il = ty*4 + ii;
            int ig = i0 + il;
            #pragma unroll
            for (int jj = 0; jj < 4; jj++) {
                int jl = tx*4 + jj;
                int jg = j0 + jl;
                float v = 0.f;
                if (ig >= jg) v = s[ii][jj] * expf(dai[il] - daj[jl]) * dtj[jl];
                Ss[il*65 + jl] = v;
            }
        }
        __syncthreads();
        // acc += S @ x_j
        #pragma unroll 4
        for (int j = 0; j < 64; j++) {
            float a[4], bv[4];
            #pragma unroll
            for (int i = 0; i < 4; i++) a[i] = Ss[(ty*4 + i)*65 + j];
            #pragma unroll
            for (int p = 0; p < 4; p++) bv[p] = Xs[j*65 + tx*4 + p];
            #pragma unroll
            for (int i = 0; i < 4; i++)
                #pragma unroll
                for (int p = 0; p < 4; p++) acc[i][p] += a[i] * bv[p];
        }
        __syncthreads();
    }

    // epilogue: + D[h] * x_i ; write y
    float Dh = Dp[h];
    #pragma unroll
    for (int ii = 0; ii < 4; ii++) {
        int t = t0 + i0 + ty*4 + ii;
        #pragma unroll
        for (int pp = 0; pp < 4; pp++) {
            int p = tx*4 + pp;
            float xv = g_xbc[(size_t)t * CONVD + h * HEADP + p];
            g_y[(size_t)t * INTERN + h * HEADP + p] = acc[ii][pp] + Dh * xv;
        }
    }
}

// ---------------- RMS norm + silu(z) gate -> TILED tf32 output for GEMM2 ----
__global__ void normgate_kernel(const float* __restrict__ nw)
{
    int t = blockIdx.x;
    float s = 0.f;
    for (int c = threadIdx.x; c < INTERN; c += 256) {
        float v = g_y[(size_t)t * INTERN + c];
        s += v * v;
    }
    __shared__ float red[8];
    #pragma unroll
    for (int o = 16; o; o >>= 1) s += __shfl_xor_sync(0xffffffffu, s, o);
    if ((threadIdx.x & 31) == 0) red[threadIdx.x >> 5] = s;
    __syncthreads();
    if (threadIdx.x < 8) {
        float v = red[threadIdx.x];
        #pragma unroll
        for (int o = 4; o; o >>= 1) v += __shfl_xor_sync(0xffu, v, o);
        if (threadIdx.x == 0) red[0] = v;
    }
    __syncthreads();
    float inv = rsqrtf(red[0] / (float)INTERN + EPSV);

    // A-type tile addressing for row t
    int tm = t >> 4;
    int r  = t & 15;
    int grow = r & 7;
    int rb   = r >> 3;
    size_t rowbase = (size_t)tm * (INTERN >> 3) * 128;
    for (int c = threadIdx.x; c < INTERN; c += 256) {
        float v = g_y[(size_t)t * INTERN + c] * inv * nw[c];
        float z = g_zx[(size_t)t * PROJN + c];
        float val = to_tf32_rn(v * (z / (1.f + expf(-z))));
        int tk = c >> 3, cin = c & 7;
        int tq = cin & 3, cb = cin >> 2;
        size_t o = rowbase + (size_t)tk * 128 + (grow * 4 + tq) * 4 + rb + 2 * cb;
        g_yr[o] = val;
    }
}

// ---------------- launch ------------------------------------------------------
extern "C" void kernel_launch(void* const* d_in, const int* in_sizes, int n_in,
                              void* d_out, int out_size)
{
    const float* hs    = (const float*)d_in[0];
    const float* w_in  = (const float*)d_in[1];
    const float* cw    = (const float*)d_in[2];
    const float* cb    = (const float*)d_in[3];
    const float* dtb   = (const float*)d_in[4];
    const float* alog  = (const float*)d_in[5];
    const float* Dp    = (const float*)d_in[6];
    const float* nw    = (const float*)d_in[7];
    const float* w_out = (const float*)d_in[8];
    float* out = (float*)d_out;

    float *zx, *yr, *ar, *br, *cr;
    cudaGetSymbolAddress((void**)&zx, g_zx);
    cudaGetSymbolAddress((void**)&yr, g_yr);
    cudaGetSymbolAddress((void**)&ar, g_ar);
    cudaGetSymbolAddress((void**)&br, g_br);
    cudaGetSymbolAddress((void**)&cr, g_cr);

    cudaFuncSetAttribute(gemm_tf32, cudaFuncAttributeMaxDynamicSharedMemorySize, GSMEM);

    size_t ysmem = (size_t)(64*129*2 + 64*65*2 + 4*64) * sizeof(float);
    cudaFuncSetAttribute(ymain_kernel, cudaFuncAttributeMaxDynamicSharedMemorySize, (int)ysmem);

    // 0) permute + tf32-round GEMM operands into fragment-major tiles
    perm_a_kernel<<<4096, 256>>>(hs,    ar, BT, HIDN);
    perm_b_kernel<<<4096, 256>>>(w_in,  br, PROJN, HIDN);
    perm_b_kernel<<<4096, 256>>>(w_out, cr, HIDN, INTERN);

    // 1) in_proj GEMM: [4096,10304] = [4096,2048] x [10304,2048]^T
    gemm_tf32<<<dim3((PROJN + BN - 1) / BN, BT / BM), 256, GSMEM>>>(ar, br, zx, BT, PROJN, HIDN);
    // 2) conv + silu
    conv_silu_kernel<<<dim3(CONVD / 256, BT), 256>>>(cw, cb);
    // 3) dt softplus + dA cumsum
    dt_kernel<<<NBC, NHEAD>>>(dtb, alog);
    // 4) per-chunk states
    states_kernel<<<dim3(NHEAD, NBC), 256>>>();
    // 5) inter-chunk scan
    scan_kernel<<<NBATCH * NHEAD, 256>>>();
    // 6) fused diag + off + D*x
    ymain_kernel<<<dim3(CHUNK / 64, NHEAD, NBC), 256, ysmem>>>(Dp);
    // 7) rmsnorm + gate (writes tiled tf32 y)
    normgate_kernel<<<BT, 256>>>(nw);
    // 8) out_proj GEMM: [4096,2048] = [4096,4096] x [2048,4096]^T
    gemm_tf32<<<dim3(HIDN / BN, BT / BM), 256, GSMEM>>>(yr, cr, out, BT, HIDN, INTERN);
}